// round 12
// baseline (speedup 1.0000x reference)
#include <cuda_runtime.h>
#include <cuda_fp16.h>
#include <cstdint>

// ---------------------------------------------------------------------------
// SelfAttention via mma.sync (HMMA) fp16-emulated-fp32 GEMMs.
// fp32 operand = hi + lo fp16 planes; 3 pair-products (hh,hl,lh) ~2^-22.
// V proj: x_hi @ (Wv_hi + Wv_lo), 2 pairs. PV: fp16 P (rounded-sum norm), 2 pairs.
// R12: 3-pair kernels use a 256x128 CTA tile / 64x64 warp tile (6:1 MMA:LDSM).
// ---------------------------------------------------------------------------

constexpr int SEQ = 4096;
constexpr int DIM = 1024;

__device__ __half g_x2[2][(size_t)SEQ * DIM];
__device__ __half g_Wq2[2][(size_t)DIM * DIM];   // transposed [out][in]
__device__ __half g_Wk2[2][(size_t)DIM * DIM];
__device__ __half g_Wv2[2][(size_t)DIM * DIM];
__device__ __half g_Q2[2][(size_t)SEQ * DIM];
__device__ __half g_K2[2][(size_t)SEQ * DIM];
__device__ float  g_V[(size_t)SEQ * DIM];
__device__ __half g_Vt2[2][(size_t)DIM * SEQ];   // [dim][seq]
__device__ float  g_P[(size_t)SEQ * SEQ];        // logits
__device__ __half g_Ph[(size_t)SEQ * SEQ];       // fp16 unnormalized probs
__device__ float  g_rinv[SEQ];

// ---------------- helpers ---------------------------------------------------
__device__ __forceinline__ uint32_t smem_u32(const void* p) {
    uint32_t a;
    asm("{ .reg .u64 t; cvta.to.shared.u64 t, %1; cvt.u32.u64 %0, t; }"
        : "=r"(a) : "l"(p));
    return a;
}
__device__ __forceinline__ void cp16(uint32_t s, const void* g) {
    asm volatile("cp.async.cg.shared.global [%0], [%1], 16;" :: "r"(s), "l"(g));
}
#define CP_COMMIT() asm volatile("cp.async.commit_group;" ::: "memory")
#define CP_WAIT1()  asm volatile("cp.async.wait_group 1;" ::: "memory")
#define CP_WAIT0()  asm volatile("cp.async.wait_group 0;" ::: "memory")

__device__ __forceinline__ void ldsm4(uint32_t* r, uint32_t addr) {
    asm volatile("ldmatrix.sync.aligned.m8n8.x4.shared.b16 {%0,%1,%2,%3}, [%4];"
                 : "=r"(r[0]), "=r"(r[1]), "=r"(r[2]), "=r"(r[3]) : "r"(addr));
}
__device__ __forceinline__ void mma16816(float* d, const uint32_t* a, const uint32_t* b) {
    asm volatile(
        "mma.sync.aligned.m16n8k16.row.col.f32.f16.f16.f32 "
        "{%0,%1,%2,%3}, {%4,%5,%6,%7}, {%8,%9}, {%0,%1,%2,%3};"
        : "+f"(d[0]), "+f"(d[1]), "+f"(d[2]), "+f"(d[3])
        : "r"(a[0]), "r"(a[1]), "r"(a[2]), "r"(a[3]), "r"(b[0]), "r"(b[1]));
}

__device__ __forceinline__ void split2h(float v, __half& a, __half& b) {
    a = __float2half_rn(v);
    b = __float2half_rn(v - __half2float(a));
}

// ========== R11 kernel (unchanged) — used for V proj and PV ==================
template <int NA, int NB, int NPAIR, int EPI, bool KLIMF, bool COMPACT>
__global__ __launch_bounds__(256, 2)
void hmma_gemm(const __half* __restrict__ A0, const __half* __restrict__ A1,
               const __half* __restrict__ B0, const __half* __restrict__ B1,
               int lda, int ldb, int K,
               float* __restrict__ Cf,
               __half* __restrict__ O0, __half* __restrict__ O1,
               int ldc, const float* __restrict__ rinv)
{
    int bn, bm;
    if (COMPACT) {
        int t = blockIdx.x;
        bm = (int)((sqrtf(8.0f * t + 1.0f) - 1.0f) * 0.5f);
        while ((bm + 1) * (bm + 2) / 2 <= t) bm++;
        while (bm * (bm + 1) / 2 > t) bm--;
        bn = t - bm * (bm + 1) / 2;
    } else {
        bn = blockIdx.x; bm = blockIdx.y;
    }
    const int m0 = bm * 128, n0 = bn * 128;

    constexpr int NPL = NA + NB;
    constexpr uint32_t RSTR = 80;
    constexpr uint32_t PLSZ = 128 * RSTR;
    constexpr uint32_t STAGE = NPL * PLSZ;

    extern __shared__ char smem_dyn[];
    const uint32_t sbase = (smem_u32(smem_dyn) + 1023u) & ~1023u;

    const int tid  = threadIdx.x;
    const int lane = tid & 31;
    const int wid  = tid >> 5;
    const int wm   = (wid >> 2) * 64;
    const int wn   = (wid & 3) * 32;

    const __half* pl[NPL];
    pl[0] = A0; if (NA > 1) pl[1] = A1;
    pl[NA] = B0; if (NB > 1) pl[NA + 1] = B1;

    int Kend = K;
    if (KLIMF) { int kl = (bm + 1) * 128; Kend = kl < K ? kl : K; }
    const int nch = Kend >> 5;

    auto load_stage = [&](int c, int buf) {
        const int k0 = c << 5;
        const uint32_t sb = sbase + buf * STAGE;
#pragma unroll
        for (int t = 0; t < NPL * 2; t++) {
            int idx = tid + t * 256;
            int plane = idx >> 9;
            int rem = idx & 511;
            int row = rem >> 2;
            int c4 = rem & 3;
            int rbase = (plane < NA) ? m0 : n0;
            int ld    = (plane < NA) ? lda : ldb;
            const __half* g = pl[plane] + (size_t)(rbase + row) * ld + k0 + c4 * 8;
            cp16(sb + plane * PLSZ + row * RSTR + c4 * 16, g);
        }
        CP_COMMIT();
    };

    float acc[4][4][4];
#pragma unroll
    for (int i = 0; i < 4; i++)
#pragma unroll
        for (int j = 0; j < 4; j++)
#pragma unroll
            for (int q = 0; q < 4; q++) acc[i][j][q] = 0.0f;

    constexpr int paA[3] = {0, 0, 1};
    constexpr int paB[3] = {0, 1, 0};

    load_stage(0, 0);
    if (nch > 1) load_stage(1, 1);

    for (int c = 0; c < nch; c++) {
        if (c + 1 < nch) { CP_WAIT1(); } else { CP_WAIT0(); }
        __syncthreads();

        const uint32_t sb = sbase + (c & 1) * STAGE;
        const uint32_t a_row = (uint32_t)(wm + (lane & 15));
        const uint32_t a_kb  = ((uint32_t)(lane >> 4)) << 4;
        const uint32_t b_row = (uint32_t)(wn + ((lane >> 1) & 8) + (lane & 7));
        const uint32_t b_kb  = ((uint32_t)((lane >> 3) & 1)) << 4;

#pragma unroll
        for (int k16 = 0; k16 < 2; k16++) {
            uint32_t bfr[NB][8];
#pragma unroll
            for (int p = 0; p < NB; p++) {
                const uint32_t pbn = sb + (NA + p) * PLSZ + k16 * 32 + b_kb;
#pragma unroll
                for (int nt2 = 0; nt2 < 2; nt2++)
                    ldsm4(&bfr[p][nt2 * 4], pbn + (b_row + nt2 * 16) * RSTR);
            }
#pragma unroll
            for (int ia = 0; ia < NA; ia++) {
                uint32_t af[4][4];
                const uint32_t pbm = sb + ia * PLSZ + k16 * 32 + a_kb;
#pragma unroll
                for (int mt = 0; mt < 4; mt++)
                    ldsm4(af[mt], pbm + (a_row + mt * 16) * RSTR);
#pragma unroll
                for (int p = 0; p < NPAIR; p++) {
                    if (paA[p] != ia) continue;
                    const int ib = paB[p];
#pragma unroll
                    for (int mt = 0; mt < 4; mt++)
#pragma unroll
                        for (int nt = 0; nt < 4; nt++)
                            mma16816(acc[mt][nt], af[mt], &bfr[ib][nt * 2]);
                }
            }
        }
        __syncthreads();
        if (c + 2 < nch) load_stage(c + 2, c & 1);
    }

#pragma unroll
    for (int mt = 0; mt < 4; mt++) {
#pragma unroll
        for (int nt = 0; nt < 4; nt++) {
            const int gm = m0 + wm + mt * 16 + (lane >> 2);
            const int gn = n0 + wn + nt * 8 + (lane & 3) * 2;
            float c0 = acc[mt][nt][0], c1 = acc[mt][nt][1];
            float c2 = acc[mt][nt][2], c3 = acc[mt][nt][3];
            if (EPI == 0) {
                *reinterpret_cast<float2*>(&Cf[(size_t)gm * ldc + gn]) = make_float2(c0, c1);
                *reinterpret_cast<float2*>(&Cf[(size_t)(gm + 8) * ldc + gn]) = make_float2(c2, c3);
            } else if (EPI == 2) {
                float s0 = rinv[gm], s1 = rinv[gm + 8];
                *reinterpret_cast<float2*>(&Cf[(size_t)gm * ldc + gn]) =
                    make_float2(c0 * s0, c1 * s0);
                *reinterpret_cast<float2*>(&Cf[(size_t)(gm + 8) * ldc + gn]) =
                    make_float2(c2 * s1, c3 * s1);
            } else {
                __half a0, b0, a1, b1;
                __half2 t;
                split2h(c0, a0, b0); split2h(c1, a1, b1);
                t.x = a0; t.y = a1;
                *reinterpret_cast<__half2*>(&O0[(size_t)gm * ldc + gn]) = t;
                t.x = b0; t.y = b1;
                *reinterpret_cast<__half2*>(&O1[(size_t)gm * ldc + gn]) = t;
                split2h(c2, a0, b0); split2h(c3, a1, b1);
                t.x = a0; t.y = a1;
                *reinterpret_cast<__half2*>(&O0[(size_t)(gm + 8) * ldc + gn]) = t;
                t.x = b0; t.y = b1;
                *reinterpret_cast<__half2*>(&O1[(size_t)(gm + 8) * ldc + gn]) = t;
            }
        }
    }
}

// ========== R12 kernel: 256x128 CTA tile, 64x64 warp tile, 3 pairs ===========
// A = hi+lo planes [M,K], B = hi+lo planes [N,K]. occ 1, acc 128 regs.
// EPI: 0 = f32 C; 1 = split2 -> 2 fp16 planes. CAUSAL: skip bn > 2bm+1.
template <int EPI, bool CAUSAL>
__global__ __launch_bounds__(256, 1)
void hmma_gemm_w64(const __half* __restrict__ A0, const __half* __restrict__ A1,
                   const __half* __restrict__ B0, const __half* __restrict__ B1,
                   int lda, int ldb, int K,
                   float* __restrict__ Cf,
                   __half* __restrict__ O0, __half* __restrict__ O1,
                   int ldc)
{
    const int bn = blockIdx.x, bm = blockIdx.y;
    if (CAUSAL && bn > 2 * bm + 1) return;
    const int m0 = bm * 256, n0 = bn * 128;

    constexpr uint32_t RSTR = 80;
    constexpr uint32_t APL = 256 * RSTR;          // 20480 per A plane
    constexpr uint32_t BPL = 128 * RSTR;          // 10240 per B plane
    constexpr uint32_t STAGE = 2 * APL + 2 * BPL; // 61440

    extern __shared__ char smem_dyn[];
    const uint32_t sbase = (smem_u32(smem_dyn) + 1023u) & ~1023u;

    const int tid  = threadIdx.x;
    const int lane = tid & 31;
    const int wid  = tid >> 5;
    const int wm   = (wid >> 1) * 64;   // 4 warps tall
    const int wn   = (wid & 1) * 64;    // 2 warps wide

    const int nch = K >> 5;

    auto load_stage = [&](int c, int buf) {
        const int k0 = c << 5;
        const uint32_t sb = sbase + buf * STAGE;
#pragma unroll
        for (int t = 0; t < 12; t++) {            // 768 rows * 4 chunks / 256 thr
            int idx = tid + t * 256;
            int r  = idx >> 2;
            int c4 = idx & 3;
            const __half* g;
            uint32_t so;
            if (r < 512) {                        // A planes (256 rows each)
                int plane = r >> 8, row = r & 255;
                g  = (plane ? A1 : A0) + (size_t)(m0 + row) * lda + k0 + c4 * 8;
                so = (uint32_t)plane * APL + (uint32_t)row * RSTR + c4 * 16;
            } else {                              // B planes (128 rows each)
                int rb = r - 512;
                int plane = rb >> 7, row = rb & 127;
                g  = (plane ? B1 : B0) + (size_t)(n0 + row) * ldb + k0 + c4 * 8;
                so = 2 * APL + (uint32_t)plane * BPL + (uint32_t)row * RSTR + c4 * 16;
            }
            cp16(sb + so, g);
        }
        CP_COMMIT();
    };

    float acc[4][8][4];
#pragma unroll
    for (int i = 0; i < 4; i++)
#pragma unroll
        for (int j = 0; j < 8; j++)
#pragma unroll
            for (int q = 0; q < 4; q++) acc[i][j][q] = 0.0f;

    constexpr int paA[3] = {0, 0, 1};
    constexpr int paB[3] = {0, 1, 0};

    load_stage(0, 0);
    if (nch > 1) load_stage(1, 1);

    for (int c = 0; c < nch; c++) {
        if (c + 1 < nch) { CP_WAIT1(); } else { CP_WAIT0(); }
        __syncthreads();

        const uint32_t sb = sbase + (c & 1) * STAGE;
        const uint32_t a_row = (uint32_t)(wm + (lane & 15));
        const uint32_t a_kb  = ((uint32_t)(lane >> 4)) << 4;
        const uint32_t b_row = (uint32_t)(wn + ((lane >> 1) & 8) + (lane & 7));
        const uint32_t b_kb  = ((uint32_t)((lane >> 3) & 1)) << 4;

#pragma unroll
        for (int k16 = 0; k16 < 2; k16++) {
            uint32_t bfr[2][16];                  // 2 planes x 64 cols
#pragma unroll
            for (int p = 0; p < 2; p++) {
                const uint32_t pbn = sb + 2 * APL + p * BPL + k16 * 32 + b_kb;
#pragma unroll
                for (int nt2 = 0; nt2 < 4; nt2++)
                    ldsm4(&bfr[p][nt2 * 4], pbn + (b_row + nt2 * 16) * RSTR);
            }
#pragma unroll
            for (int ia = 0; ia < 2; ia++) {
                uint32_t af[4][4];
                const uint32_t pbm = sb + ia * APL + k16 * 32 + a_kb;
#pragma unroll
                for (int mt = 0; mt < 4; mt++)
                    ldsm4(af[mt], pbm + (a_row + mt * 16) * RSTR);
#pragma unroll
                for (int p = 0; p < 3; p++) {
                    if (paA[p] != ia) continue;
                    const int ib = paB[p];
#pragma unroll
                    for (int mt = 0; mt < 4; mt++)
#pragma unroll
                        for (int nt = 0; nt < 8; nt++)
                            mma16816(acc[mt][nt], af[mt], &bfr[ib][nt * 2]);
                }
            }
        }
        __syncthreads();
        if (c + 2 < nch) load_stage(c + 2, c & 1);
    }

#pragma unroll
    for (int mt = 0; mt < 4; mt++) {
#pragma unroll
        for (int nt = 0; nt < 8; nt++) {
            const int gm = m0 + wm + mt * 16 + (lane >> 2);
            const int gn = n0 + wn + nt * 8 + (lane & 3) * 2;
            float c0 = acc[mt][nt][0], c1 = acc[mt][nt][1];
            float c2 = acc[mt][nt][2], c3 = acc[mt][nt][3];
            if (EPI == 0) {
                *reinterpret_cast<float2*>(&Cf[(size_t)gm * ldc + gn]) = make_float2(c0, c1);
                *reinterpret_cast<float2*>(&Cf[(size_t)(gm + 8) * ldc + gn]) = make_float2(c2, c3);
            } else {
                __half a0, b0, a1, b1;
                __half2 t;
                split2h(c0, a0, b0); split2h(c1, a1, b1);
                t.x = a0; t.y = a1;
                *reinterpret_cast<__half2*>(&O0[(size_t)gm * ldc + gn]) = t;
                t.x = b0; t.y = b1;
                *reinterpret_cast<__half2*>(&O1[(size_t)gm * ldc + gn]) = t;
                split2h(c2, a0, b0); split2h(c3, a1, b1);
                t.x = a0; t.y = a1;
                *reinterpret_cast<__half2*>(&O0[(size_t)(gm + 8) * ldc + gn]) = t;
                t.x = b0; t.y = b1;
                *reinterpret_cast<__half2*>(&O1[(size_t)(gm + 8) * ldc + gn]) = t;
            }
        }
    }
}

// ---------------- prep kernels ----------------------------------------------
__global__ void split2_kernel(const float* __restrict__ in, size_t n,
                              __half* __restrict__ o0, __half* __restrict__ o1)
{
    size_t i = (size_t)blockIdx.x * blockDim.x + threadIdx.x;
    size_t stride = (size_t)gridDim.x * blockDim.x;
    for (; i < n; i += stride) {
        __half a, b;
        split2h(in[i], a, b);
        o0[i] = a; o1[i] = b;
    }
}

__global__ void tsplit2_kernel(const float* __restrict__ in, int R, int C,
                               __half* __restrict__ o0, __half* __restrict__ o1)
{
    __shared__ float t[32][33];
    const int bc = blockIdx.x * 32, br = blockIdx.y * 32;
    const int tx = threadIdx.x, ty = threadIdx.y;
#pragma unroll
    for (int i = 0; i < 4; i++)
        t[ty + i * 8][tx] = in[(size_t)(br + ty + i * 8) * C + bc + tx];
    __syncthreads();
#pragma unroll
    for (int i = 0; i < 4; i++) {
        float v = t[tx][ty + i * 8];
        size_t o = (size_t)(bc + ty + i * 8) * R + br + tx;
        __half a, b;
        split2h(v, a, b);
        o0[o] = a; o1[o] = b;
    }
}

__global__ __launch_bounds__(256)
void softmax_h(const float* __restrict__ P, __half* __restrict__ Ph,
               float* __restrict__ rinv)
{
    const int row   = blockIdx.x;
    const int valid = row + 1;
    const int klim  = ((row >> 7) + 1) << 7;
    const float* prow = P + (size_t)row * SEQ;
    const int tid = threadIdx.x;
    __shared__ float red[256];

    float m = -3.402823466e38f;
    for (int j = tid; j < valid; j += 256) m = fmaxf(m, prow[j]);
    red[tid] = m;
    __syncthreads();
#pragma unroll
    for (int s = 128; s > 0; s >>= 1) {
        if (tid < s) red[tid] = fmaxf(red[tid], red[tid + s]);
        __syncthreads();
    }
    m = red[0];
    __syncthreads();

    const float inv_sqrt_d = 0.03125f;
    float sum = 0.0f;
    for (int j = tid; j < klim; j += 256) {
        float e = 0.0f;
        if (j < valid) e = __expf((prow[j] - m) * inv_sqrt_d);
        __half h = __float2half_rn(e);
        Ph[(size_t)row * SEQ + j] = h;
        sum += __half2float(h);
    }
    red[tid] = sum;
    __syncthreads();
#pragma unroll
    for (int s = 128; s > 0; s >>= 1) {
        if (tid < s) red[tid] += red[tid + s];
        __syncthreads();
    }
    if (tid == 0) rinv[row] = 1.0f / red[0];
}

// ---------------- host side --------------------------------------------------
extern "C" void kernel_launch(void* const* d_in, const int* in_sizes, int n_in,
                              void* d_out, int out_size)
{
    const float* x  = (const float*)d_in[0];
    const float* Wq = (const float*)d_in[1];
    const float* Wk = (const float*)d_in[2];
    const float* Wv = (const float*)d_in[3];
    float* out = (float*)d_out;

    __half *x2[2], *Wq2[2], *Wk2[2], *Wv2[2], *Q2[2], *K2[2], *Vt2[2];
    __half *Ph;
    float *V, *P, *rinv;
    for (int i = 0; i < 2; i++) {
        cudaGetSymbolAddress((void**)&x2[i],  g_x2);  x2[i]  += (size_t)i * SEQ * DIM;
        cudaGetSymbolAddress((void**)&Wq2[i], g_Wq2); Wq2[i] += (size_t)i * DIM * DIM;
        cudaGetSymbolAddress((void**)&Wk2[i], g_Wk2); Wk2[i] += (size_t)i * DIM * DIM;
        cudaGetSymbolAddress((void**)&Wv2[i], g_Wv2); Wv2[i] += (size_t)i * DIM * DIM;
        cudaGetSymbolAddress((void**)&Q2[i],  g_Q2);  Q2[i]  += (size_t)i * SEQ * DIM;
        cudaGetSymbolAddress((void**)&K2[i],  g_K2);  K2[i]  += (size_t)i * SEQ * DIM;
        cudaGetSymbolAddress((void**)&Vt2[i], g_Vt2); Vt2[i] += (size_t)i * DIM * SEQ;
    }
    cudaGetSymbolAddress((void**)&Ph,   g_Ph);
    cudaGetSymbolAddress((void**)&V,    g_V);
    cudaGetSymbolAddress((void**)&P,    g_P);
    cudaGetSymbolAddress((void**)&rinv, g_rinv);

    auto gemm_proj   = hmma_gemm_w64<1, false>;              // Q/K proj (w64 tile)
    auto gemm_causal = hmma_gemm_w64<0, true>;               // QK^T (w64 tile)
    auto gemm_vproj  = hmma_gemm<1, 2, 2, 0, false, false>;  // V proj (2-pair)
    auto gemm_pv     = hmma_gemm<1, 2, 2, 2, true,  false>;  // PV -> out (K-limit)

    const int SMW = 2 * 61440 + 1024;   // 123904 (w64 kernels)
    const int SM3 = 2 * 3 * 10240 + 1024;   // 62464
    cudaFuncSetAttribute(gemm_proj,   cudaFuncAttributeMaxDynamicSharedMemorySize, SMW);
    cudaFuncSetAttribute(gemm_causal, cudaFuncAttributeMaxDynamicSharedMemorySize, SMW);
    cudaFuncSetAttribute(gemm_vproj,  cudaFuncAttributeMaxDynamicSharedMemorySize, SM3);
    cudaFuncSetAttribute(gemm_pv,     cudaFuncAttributeMaxDynamicSharedMemorySize, SM3);

    // 1) operand splits
    split2_kernel<<<1024, 256>>>(x, (size_t)SEQ * DIM, x2[0], x2[1]);
    dim3 tb(32, 8);
    tsplit2_kernel<<<dim3(DIM / 32, DIM / 32), tb>>>(Wq, DIM, DIM, Wq2[0], Wq2[1]);
    tsplit2_kernel<<<dim3(DIM / 32, DIM / 32), tb>>>(Wk, DIM, DIM, Wk2[0], Wk2[1]);
    tsplit2_kernel<<<dim3(DIM / 32, DIM / 32), tb>>>(Wv, DIM, DIM, Wv2[0], Wv2[1]);

    dim3 gProjW(DIM / 128, SEQ / 256);    // (8, 16) w64 tile
    dim3 gProj(DIM / 128, SEQ / 128);     // (8, 32) legacy tile

    // 2) projections
    gemm_proj<<<gProjW, 256, SMW>>>(x2[0], x2[1], Wq2[0], Wq2[1],
                                    DIM, DIM, DIM, nullptr, Q2[0], Q2[1], DIM);
    gemm_proj<<<gProjW, 256, SMW>>>(x2[0], x2[1], Wk2[0], Wk2[1],
                                    DIM, DIM, DIM, nullptr, K2[0], K2[1], DIM);
    gemm_vproj<<<gProj, 256, SM3>>>(x2[0], nullptr, Wv2[0], Wv2[1],
                                    DIM, DIM, DIM, V, nullptr, nullptr, DIM, nullptr);

    // 3) V -> Vt (split2, transposed)
    tsplit2_kernel<<<dim3(DIM / 32, SEQ / 32), tb>>>(V, SEQ, DIM, Vt2[0], Vt2[1]);

    // 4) logits: 256x128 tiles, causal early-exit (272 of 512 CTAs work)
    gemm_causal<<<dim3(SEQ / 128, SEQ / 256), 256, SMW>>>(Q2[0], Q2[1], K2[0], K2[1],
                                                          DIM, DIM, DIM, P, nullptr, nullptr, SEQ);

    // 5) softmax -> fp16 probs + rinv of rounded sum
    softmax_h<<<SEQ, 256>>>(P, Ph, rinv);

    // 6) out = (Ph @ V) * rinv, causal K-limit
    gemm_pv<<<gProj, 256, SM3>>>(Ph, nullptr, Vt2[0], Vt2[1],
                                 SEQ, SEQ, SEQ, out, nullptr, nullptr, DIM, rinv);
}

// round 13
// speedup vs baseline: 1.0530x; 1.0530x over previous
#include <cuda_runtime.h>
#include <cuda_fp16.h>
#include <cstdint>

// ---------------------------------------------------------------------------
// SelfAttention via mma.sync (HMMA) fp16-emulated-fp32 GEMMs.
// fp32 operand = hi + lo fp16 planes; 3 pair-products (hh,hl,lh) ~2^-22.
// V proj: x_hi @ (Wv_hi + Wv_lo), 2 pairs. PV: fp16 P (rounded-sum norm), 2 pairs.
// R13: Q/K/V projections merged into ONE launch (gridDim.z=3) to kill the
// 3x back-to-back 86%-full waves (256 CTAs vs 296 slots each).
// ---------------------------------------------------------------------------

constexpr int SEQ = 4096;
constexpr int DIM = 1024;

__device__ __half g_x2[2][(size_t)SEQ * DIM];
__device__ __half g_Wq2[2][(size_t)DIM * DIM];   // transposed [out][in]
__device__ __half g_Wk2[2][(size_t)DIM * DIM];
__device__ __half g_Wv2[2][(size_t)DIM * DIM];
__device__ __half g_Q2[2][(size_t)SEQ * DIM];
__device__ __half g_K2[2][(size_t)SEQ * DIM];
__device__ float  g_V[(size_t)SEQ * DIM];
__device__ __half g_Vt2[2][(size_t)DIM * SEQ];   // [dim][seq]
__device__ float  g_P[(size_t)SEQ * SEQ];        // logits
__device__ __half g_Ph[(size_t)SEQ * SEQ];       // fp16 unnormalized probs
__device__ float  g_rinv[SEQ];

// ---------------- helpers ---------------------------------------------------
__device__ __forceinline__ uint32_t smem_u32(const void* p) {
    uint32_t a;
    asm("{ .reg .u64 t; cvta.to.shared.u64 t, %1; cvt.u32.u64 %0, t; }"
        : "=r"(a) : "l"(p));
    return a;
}
__device__ __forceinline__ void cp16(uint32_t s, const void* g) {
    asm volatile("cp.async.cg.shared.global [%0], [%1], 16;" :: "r"(s), "l"(g));
}
#define CP_COMMIT() asm volatile("cp.async.commit_group;" ::: "memory")
#define CP_WAIT1()  asm volatile("cp.async.wait_group 1;" ::: "memory")
#define CP_WAIT0()  asm volatile("cp.async.wait_group 0;" ::: "memory")

__device__ __forceinline__ void ldsm4(uint32_t* r, uint32_t addr) {
    asm volatile("ldmatrix.sync.aligned.m8n8.x4.shared.b16 {%0,%1,%2,%3}, [%4];"
                 : "=r"(r[0]), "=r"(r[1]), "=r"(r[2]), "=r"(r[3]) : "r"(addr));
}
__device__ __forceinline__ void mma16816(float* d, const uint32_t* a, const uint32_t* b) {
    asm volatile(
        "mma.sync.aligned.m16n8k16.row.col.f32.f16.f16.f32 "
        "{%0,%1,%2,%3}, {%4,%5,%6,%7}, {%8,%9}, {%0,%1,%2,%3};"
        : "+f"(d[0]), "+f"(d[1]), "+f"(d[2]), "+f"(d[3])
        : "r"(a[0]), "r"(a[1]), "r"(a[2]), "r"(a[3]), "r"(b[0]), "r"(b[1]));
}

__device__ __forceinline__ void split2h(float v, __half& a, __half& b) {
    a = __float2half_rn(v);
    b = __float2half_rn(v - __half2float(a));
}

// ========== R11 generic kernel — used for QK^T and PV (unchanged) ============
template <int NA, int NB, int NPAIR, int EPI, bool KLIMF, bool COMPACT>
__global__ __launch_bounds__(256, 2)
void hmma_gemm(const __half* __restrict__ A0, const __half* __restrict__ A1,
               const __half* __restrict__ B0, const __half* __restrict__ B1,
               int lda, int ldb, int K,
               float* __restrict__ Cf,
               __half* __restrict__ O0, __half* __restrict__ O1,
               int ldc, const float* __restrict__ rinv)
{
    int bn, bm;
    if (COMPACT) {
        int t = blockIdx.x;
        bm = (int)((sqrtf(8.0f * t + 1.0f) - 1.0f) * 0.5f);
        while ((bm + 1) * (bm + 2) / 2 <= t) bm++;
        while (bm * (bm + 1) / 2 > t) bm--;
        bn = t - bm * (bm + 1) / 2;
    } else {
        bn = blockIdx.x; bm = blockIdx.y;
    }
    const int m0 = bm * 128, n0 = bn * 128;

    constexpr int NPL = NA + NB;
    constexpr uint32_t RSTR = 80;
    constexpr uint32_t PLSZ = 128 * RSTR;
    constexpr uint32_t STAGE = NPL * PLSZ;

    extern __shared__ char smem_dyn[];
    const uint32_t sbase = (smem_u32(smem_dyn) + 1023u) & ~1023u;

    const int tid  = threadIdx.x;
    const int lane = tid & 31;
    const int wid  = tid >> 5;
    const int wm   = (wid >> 2) * 64;
    const int wn   = (wid & 3) * 32;

    const __half* pl[NPL];
    pl[0] = A0; if (NA > 1) pl[1] = A1;
    pl[NA] = B0; if (NB > 1) pl[NA + 1] = B1;

    int Kend = K;
    if (KLIMF) { int kl = (bm + 1) * 128; Kend = kl < K ? kl : K; }
    const int nch = Kend >> 5;

    auto load_stage = [&](int c, int buf) {
        const int k0 = c << 5;
        const uint32_t sb = sbase + buf * STAGE;
#pragma unroll
        for (int t = 0; t < NPL * 2; t++) {
            int idx = tid + t * 256;
            int plane = idx >> 9;
            int rem = idx & 511;
            int row = rem >> 2;
            int c4 = rem & 3;
            int rbase = (plane < NA) ? m0 : n0;
            int ld    = (plane < NA) ? lda : ldb;
            const __half* g = pl[plane] + (size_t)(rbase + row) * ld + k0 + c4 * 8;
            cp16(sb + plane * PLSZ + row * RSTR + c4 * 16, g);
        }
        CP_COMMIT();
    };

    float acc[4][4][4];
#pragma unroll
    for (int i = 0; i < 4; i++)
#pragma unroll
        for (int j = 0; j < 4; j++)
#pragma unroll
            for (int q = 0; q < 4; q++) acc[i][j][q] = 0.0f;

    constexpr int paA[3] = {0, 0, 1};
    constexpr int paB[3] = {0, 1, 0};

    load_stage(0, 0);
    if (nch > 1) load_stage(1, 1);

    for (int c = 0; c < nch; c++) {
        if (c + 1 < nch) { CP_WAIT1(); } else { CP_WAIT0(); }
        __syncthreads();

        const uint32_t sb = sbase + (c & 1) * STAGE;
        const uint32_t a_row = (uint32_t)(wm + (lane & 15));
        const uint32_t a_kb  = ((uint32_t)(lane >> 4)) << 4;
        const uint32_t b_row = (uint32_t)(wn + ((lane >> 1) & 8) + (lane & 7));
        const uint32_t b_kb  = ((uint32_t)((lane >> 3) & 1)) << 4;

#pragma unroll
        for (int k16 = 0; k16 < 2; k16++) {
            uint32_t bfr[NB][8];
#pragma unroll
            for (int p = 0; p < NB; p++) {
                const uint32_t pbn = sb + (NA + p) * PLSZ + k16 * 32 + b_kb;
#pragma unroll
                for (int nt2 = 0; nt2 < 2; nt2++)
                    ldsm4(&bfr[p][nt2 * 4], pbn + (b_row + nt2 * 16) * RSTR);
            }
#pragma unroll
            for (int ia = 0; ia < NA; ia++) {
                uint32_t af[4][4];
                const uint32_t pbm = sb + ia * PLSZ + k16 * 32 + a_kb;
#pragma unroll
                for (int mt = 0; mt < 4; mt++)
                    ldsm4(af[mt], pbm + (a_row + mt * 16) * RSTR);
#pragma unroll
                for (int p = 0; p < NPAIR; p++) {
                    if (paA[p] != ia) continue;
                    const int ib = paB[p];
#pragma unroll
                    for (int mt = 0; mt < 4; mt++)
#pragma unroll
                        for (int nt = 0; nt < 4; nt++)
                            mma16816(acc[mt][nt], af[mt], &bfr[ib][nt * 2]);
                }
            }
        }
        __syncthreads();
        if (c + 2 < nch) load_stage(c + 2, c & 1);
    }

#pragma unroll
    for (int mt = 0; mt < 4; mt++) {
#pragma unroll
        for (int nt = 0; nt < 4; nt++) {
            const int gm = m0 + wm + mt * 16 + (lane >> 2);
            const int gn = n0 + wn + nt * 8 + (lane & 3) * 2;
            float c0 = acc[mt][nt][0], c1 = acc[mt][nt][1];
            float c2 = acc[mt][nt][2], c3 = acc[mt][nt][3];
            if (EPI == 0) {
                *reinterpret_cast<float2*>(&Cf[(size_t)gm * ldc + gn]) = make_float2(c0, c1);
                *reinterpret_cast<float2*>(&Cf[(size_t)(gm + 8) * ldc + gn]) = make_float2(c2, c3);
            } else if (EPI == 2) {
                float s0 = rinv[gm], s1 = rinv[gm + 8];
                *reinterpret_cast<float2*>(&Cf[(size_t)gm * ldc + gn]) =
                    make_float2(c0 * s0, c1 * s0);
                *reinterpret_cast<float2*>(&Cf[(size_t)(gm + 8) * ldc + gn]) =
                    make_float2(c2 * s1, c3 * s1);
            } else {
                __half a0, b0, a1, b1;
                __half2 t;
                split2h(c0, a0, b0); split2h(c1, a1, b1);
                t.x = a0; t.y = a1;
                *reinterpret_cast<__half2*>(&O0[(size_t)gm * ldc + gn]) = t;
                t.x = b0; t.y = b1;
                *reinterpret_cast<__half2*>(&O1[(size_t)gm * ldc + gn]) = t;
                split2h(c2, a0, b0); split2h(c3, a1, b1);
                t.x = a0; t.y = a1;
                *reinterpret_cast<__half2*>(&O0[(size_t)(gm + 8) * ldc + gn]) = t;
                t.x = b0; t.y = b1;
                *reinterpret_cast<__half2*>(&O1[(size_t)(gm + 8) * ldc + gn]) = t;
            }
        }
    }
}

// ========== R13: merged Q/K/V projection (one launch, gridDim.z = 3) =========
// z=0: Q = x @ Wq^T (3 pairs, split2 -> Q planes)
// z=1: K = x @ Wk^T (3 pairs, split2 -> K planes)
// z=2: V = x_hi @ (Wv_hi + Wv_lo) (2 pairs, f32 -> V)
// Load loop is identical for all z (4 planes); z only gates pairs + epilogue.
__global__ __launch_bounds__(256, 2)
void proj3_kernel(const __half* __restrict__ x0, const __half* __restrict__ x1,
                  const __half* __restrict__ Wq0, const __half* __restrict__ Wq1,
                  const __half* __restrict__ Wk0, const __half* __restrict__ Wk1,
                  const __half* __restrict__ Wv0, const __half* __restrict__ Wv1,
                  __half* __restrict__ Q0, __half* __restrict__ Q1,
                  __half* __restrict__ K0, __half* __restrict__ K1,
                  float* __restrict__ Vf)
{
    const int bn = blockIdx.x, bm = blockIdx.y, z = blockIdx.z;
    const int m0 = bm * 128, n0 = bn * 128;

    const __half* B0 = (z == 0) ? Wq0 : (z == 1) ? Wk0 : Wv0;
    const __half* B1 = (z == 0) ? Wq1 : (z == 1) ? Wk1 : Wv1;
    __half* O0 = (z == 0) ? Q0 : K0;
    __half* O1 = (z == 0) ? Q1 : K1;

    constexpr uint32_t RSTR = 80;
    constexpr uint32_t PLSZ = 128 * RSTR;
    constexpr uint32_t STAGE = 4 * PLSZ;

    extern __shared__ char smem_dyn[];
    const uint32_t sbase = (smem_u32(smem_dyn) + 1023u) & ~1023u;

    const int tid  = threadIdx.x;
    const int lane = tid & 31;
    const int wid  = tid >> 5;
    const int wm   = (wid >> 2) * 64;
    const int wn   = (wid & 3) * 32;

    const __half* pl[4] = {x0, x1, B0, B1};
    const int nch = DIM >> 5;   // 32

    auto load_stage = [&](int c, int buf) {
        const int k0 = c << 5;
        const uint32_t sb = sbase + buf * STAGE;
#pragma unroll
        for (int t = 0; t < 8; t++) {
            int idx = tid + t * 256;
            int plane = idx >> 9;
            int rem = idx & 511;
            int row = rem >> 2;
            int c4 = rem & 3;
            int rbase = (plane < 2) ? m0 : n0;
            const __half* g = pl[plane] + (size_t)(rbase + row) * DIM + k0 + c4 * 8;
            cp16(sb + plane * PLSZ + row * RSTR + c4 * 16, g);
        }
        CP_COMMIT();
    };

    float acc[4][4][4];
#pragma unroll
    for (int i = 0; i < 4; i++)
#pragma unroll
        for (int j = 0; j < 4; j++)
#pragma unroll
            for (int q = 0; q < 4; q++) acc[i][j][q] = 0.0f;

    load_stage(0, 0);
    load_stage(1, 1);

    for (int c = 0; c < nch; c++) {
        if (c + 1 < nch) { CP_WAIT1(); } else { CP_WAIT0(); }
        __syncthreads();

        const uint32_t sb = sbase + (c & 1) * STAGE;
        const uint32_t a_row = (uint32_t)(wm + (lane & 15));
        const uint32_t a_kb  = ((uint32_t)(lane >> 4)) << 4;
        const uint32_t b_row = (uint32_t)(wn + ((lane >> 1) & 8) + (lane & 7));
        const uint32_t b_kb  = ((uint32_t)((lane >> 3) & 1)) << 4;

#pragma unroll
        for (int k16 = 0; k16 < 2; k16++) {
            uint32_t bfr[2][8];
#pragma unroll
            for (int p = 0; p < 2; p++) {
                const uint32_t pbn = sb + (2 + p) * PLSZ + k16 * 32 + b_kb;
#pragma unroll
                for (int nt2 = 0; nt2 < 2; nt2++)
                    ldsm4(&bfr[p][nt2 * 4], pbn + (b_row + nt2 * 16) * RSTR);
            }
            // A plane 0: pairs (0,B0) and (0,B1) — all z
            {
                uint32_t af[4][4];
                const uint32_t pbm = sb + k16 * 32 + a_kb;
#pragma unroll
                for (int mt = 0; mt < 4; mt++)
                    ldsm4(af[mt], pbm + (a_row + mt * 16) * RSTR);
#pragma unroll
                for (int ib = 0; ib < 2; ib++)
#pragma unroll
                    for (int mt = 0; mt < 4; mt++)
#pragma unroll
                        for (int nt = 0; nt < 4; nt++)
                            mma16816(acc[mt][nt], af[mt], &bfr[ib][nt * 2]);
            }
            // A plane 1: pair (1,B0) — Q/K only (uniform branch)
            if (z < 2) {
                uint32_t af[4][4];
                const uint32_t pbm = sb + PLSZ + k16 * 32 + a_kb;
#pragma unroll
                for (int mt = 0; mt < 4; mt++)
                    ldsm4(af[mt], pbm + (a_row + mt * 16) * RSTR);
#pragma unroll
                for (int mt = 0; mt < 4; mt++)
#pragma unroll
                    for (int nt = 0; nt < 4; nt++)
                        mma16816(acc[mt][nt], af[mt], &bfr[0][nt * 2]);
            }
        }
        __syncthreads();
        if (c + 2 < nch) load_stage(c + 2, c & 1);
    }

#pragma unroll
    for (int mt = 0; mt < 4; mt++) {
#pragma unroll
        for (int nt = 0; nt < 4; nt++) {
            const int gm = m0 + wm + mt * 16 + (lane >> 2);
            const int gn = n0 + wn + nt * 8 + (lane & 3) * 2;
            float c0 = acc[mt][nt][0], c1 = acc[mt][nt][1];
            float c2 = acc[mt][nt][2], c3 = acc[mt][nt][3];
            if (z == 2) {
                *reinterpret_cast<float2*>(&Vf[(size_t)gm * DIM + gn]) = make_float2(c0, c1);
                *reinterpret_cast<float2*>(&Vf[(size_t)(gm + 8) * DIM + gn]) = make_float2(c2, c3);
            } else {
                __half a0, b0, a1, b1;
                __half2 t;
                split2h(c0, a0, b0); split2h(c1, a1, b1);
                t.x = a0; t.y = a1;
                *reinterpret_cast<__half2*>(&O0[(size_t)gm * DIM + gn]) = t;
                t.x = b0; t.y = b1;
                *reinterpret_cast<__half2*>(&O1[(size_t)gm * DIM + gn]) = t;
                split2h(c2, a0, b0); split2h(c3, a1, b1);
                t.x = a0; t.y = a1;
                *reinterpret_cast<__half2*>(&O0[(size_t)(gm + 8) * DIM + gn]) = t;
                t.x = b0; t.y = b1;
                *reinterpret_cast<__half2*>(&O1[(size_t)(gm + 8) * DIM + gn]) = t;
            }
        }
    }
}

// ---------------- prep kernels ----------------------------------------------
__global__ void split2_kernel(const float* __restrict__ in, size_t n,
                              __half* __restrict__ o0, __half* __restrict__ o1)
{
    size_t i = (size_t)blockIdx.x * blockDim.x + threadIdx.x;
    size_t stride = (size_t)gridDim.x * blockDim.x;
    for (; i < n; i += stride) {
        __half a, b;
        split2h(in[i], a, b);
        o0[i] = a; o1[i] = b;
    }
}

// merged transpose + split2 of the 3 weight matrices (z selects which)
__global__ void tsplitW_kernel(const float* __restrict__ Wq, const float* __restrict__ Wk,
                               const float* __restrict__ Wv,
                               __half* __restrict__ q0, __half* __restrict__ q1,
                               __half* __restrict__ k0, __half* __restrict__ k1,
                               __half* __restrict__ v0, __half* __restrict__ v1)
{
    const float* in = (blockIdx.z == 0) ? Wq : (blockIdx.z == 1) ? Wk : Wv;
    __half* o0 = (blockIdx.z == 0) ? q0 : (blockIdx.z == 1) ? k0 : v0;
    __half* o1 = (blockIdx.z == 0) ? q1 : (blockIdx.z == 1) ? k1 : v1;
    __shared__ float t[32][33];
    const int bc = blockIdx.x * 32, br = blockIdx.y * 32;
    const int tx = threadIdx.x, ty = threadIdx.y;
#pragma unroll
    for (int i = 0; i < 4; i++)
        t[ty + i * 8][tx] = in[(size_t)(br + ty + i * 8) * DIM + bc + tx];
    __syncthreads();
#pragma unroll
    for (int i = 0; i < 4; i++) {
        float v = t[tx][ty + i * 8];
        size_t o = (size_t)(bc + ty + i * 8) * DIM + br + tx;
        __half a, b;
        split2h(v, a, b);
        o0[o] = a; o1[o] = b;
    }
}

// transpose + split2: V [SEQ, DIM] f32 -> planes [DIM, SEQ] fp16
__global__ void tsplitV_kernel(const float* __restrict__ in,
                               __half* __restrict__ o0, __half* __restrict__ o1)
{
    __shared__ float t[32][33];
    const int bc = blockIdx.x * 32, br = blockIdx.y * 32;
    const int tx = threadIdx.x, ty = threadIdx.y;
#pragma unroll
    for (int i = 0; i < 4; i++)
        t[ty + i * 8][tx] = in[(size_t)(br + ty + i * 8) * DIM + bc + tx];
    __syncthreads();
#pragma unroll
    for (int i = 0; i < 4; i++) {
        float v = t[tx][ty + i * 8];
        size_t o = (size_t)(bc + ty + i * 8) * SEQ + br + tx;
        __half a, b;
        split2h(v, a, b);
        o0[o] = a; o1[o] = b;
    }
}

__global__ __launch_bounds__(256)
void softmax_h(const float* __restrict__ P, __half* __restrict__ Ph,
               float* __restrict__ rinv)
{
    const int row   = blockIdx.x;
    const int valid = row + 1;
    const int klim  = ((row >> 7) + 1) << 7;
    const float* prow = P + (size_t)row * SEQ;
    const int tid = threadIdx.x;
    __shared__ float red[256];

    float m = -3.402823466e38f;
    for (int j = tid; j < valid; j += 256) m = fmaxf(m, prow[j]);
    red[tid] = m;
    __syncthreads();
#pragma unroll
    for (int s = 128; s > 0; s >>= 1) {
        if (tid < s) red[tid] = fmaxf(red[tid], red[tid + s]);
        __syncthreads();
    }
    m = red[0];
    __syncthreads();

    const float inv_sqrt_d = 0.03125f;
    float sum = 0.0f;
    for (int j = tid; j < klim; j += 256) {
        float e = 0.0f;
        if (j < valid) e = __expf((prow[j] - m) * inv_sqrt_d);
        __half h = __float2half_rn(e);
        Ph[(size_t)row * SEQ + j] = h;
        sum += __half2float(h);
    }
    red[tid] = sum;
    __syncthreads();
#pragma unroll
    for (int s = 128; s > 0; s >>= 1) {
        if (tid < s) red[tid] += red[tid + s];
        __syncthreads();
    }
    if (tid == 0) rinv[row] = 1.0f / red[0];
}

// ---------------- host side --------------------------------------------------
extern "C" void kernel_launch(void* const* d_in, const int* in_sizes, int n_in,
                              void* d_out, int out_size)
{
    const float* x  = (const float*)d_in[0];
    const float* Wq = (const float*)d_in[1];
    const float* Wk = (const float*)d_in[2];
    const float* Wv = (const float*)d_in[3];
    float* out = (float*)d_out;

    __half *x2[2], *Wq2[2], *Wk2[2], *Wv2[2], *Q2[2], *K2[2], *Vt2[2];
    __half *Ph;
    float *V, *P, *rinv;
    for (int i = 0; i < 2; i++) {
        cudaGetSymbolAddress((void**)&x2[i],  g_x2);  x2[i]  += (size_t)i * SEQ * DIM;
        cudaGetSymbolAddress((void**)&Wq2[i], g_Wq2); Wq2[i] += (size_t)i * DIM * DIM;
        cudaGetSymbolAddress((void**)&Wk2[i], g_Wk2); Wk2[i] += (size_t)i * DIM * DIM;
        cudaGetSymbolAddress((void**)&Wv2[i], g_Wv2); Wv2[i] += (size_t)i * DIM * DIM;
        cudaGetSymbolAddress((void**)&Q2[i],  g_Q2);  Q2[i]  += (size_t)i * SEQ * DIM;
        cudaGetSymbolAddress((void**)&K2[i],  g_K2);  K2[i]  += (size_t)i * SEQ * DIM;
        cudaGetSymbolAddress((void**)&Vt2[i], g_Vt2); Vt2[i] += (size_t)i * DIM * SEQ;
    }
    cudaGetSymbolAddress((void**)&Ph,   g_Ph);
    cudaGetSymbolAddress((void**)&V,    g_V);
    cudaGetSymbolAddress((void**)&P,    g_P);
    cudaGetSymbolAddress((void**)&rinv, g_rinv);

    auto gemm_causal = hmma_gemm<2, 2, 3, 0, false, true>;   // QK^T (compact)
    auto gemm_pv     = hmma_gemm<1, 2, 2, 2, true,  false>;  // PV (K-limit)

    const int SM4 = 2 * 4 * 10240 + 1024;   // 82944
    const int SM3 = 2 * 3 * 10240 + 1024;   // 62464
    cudaFuncSetAttribute(proj3_kernel, cudaFuncAttributeMaxDynamicSharedMemorySize, SM4);
    cudaFuncSetAttribute(gemm_causal,  cudaFuncAttributeMaxDynamicSharedMemorySize, SM4);
    cudaFuncSetAttribute(gemm_pv,      cudaFuncAttributeMaxDynamicSharedMemorySize, SM3);

    // 1) operand splits
    split2_kernel<<<1024, 256>>>(x, (size_t)SEQ * DIM, x2[0], x2[1]);
    dim3 tb(32, 8);
    tsplitW_kernel<<<dim3(DIM / 32, DIM / 32, 3), tb>>>(Wq, Wk, Wv,
                                                        Wq2[0], Wq2[1], Wk2[0], Wk2[1],
                                                        Wv2[0], Wv2[1]);

    // 2) all three projections in ONE launch (768 CTAs)
    proj3_kernel<<<dim3(DIM / 128, SEQ / 128, 3), 256, SM4>>>(
        x2[0], x2[1], Wq2[0], Wq2[1], Wk2[0], Wk2[1], Wv2[0], Wv2[1],
        Q2[0], Q2[1], K2[0], K2[1], V);

    // 3) V -> Vt (split2, transposed)
    tsplitV_kernel<<<dim3(DIM / 32, SEQ / 32), tb>>>(V, Vt2[0], Vt2[1]);

    // 4) logits: compact lower-triangular grid (528 CTAs)
    gemm_causal<<<dim3(32 * 33 / 2), 256, SM4>>>(Q2[0], Q2[1], K2[0], K2[1],
                                                 DIM, DIM, DIM, P, nullptr, nullptr, SEQ, nullptr);

    // 5) softmax -> fp16 probs + rinv of rounded sum
    softmax_h<<<SEQ, 256>>>(P, Ph, rinv);

    // 6) out = (Ph @ V) * rinv, causal K-limit
    gemm_pv<<<dim3(DIM / 128, SEQ / 128), 256, SM3>>>(Ph, nullptr, Vt2[0], Vt2[1],
                                                      SEQ, SEQ, SEQ, out, nullptr, nullptr,
                                                      DIM, rinv);
}

// round 14
// speedup vs baseline: 1.0982x; 1.0430x over previous
#include <cuda_runtime.h>
#include <cuda_fp16.h>
#include <cstdint>

// ---------------------------------------------------------------------------
// SelfAttention via mma.sync (HMMA) fp16-emulated-fp32 GEMMs.
// fp32 operand = hi + lo fp16 planes; 3 pair-products (hh,hl,lh) ~2^-22.
// V proj: x_hi @ (Wv_hi + Wv_lo), 2 pairs. PV: fp16 P (rounded-sum norm), 2 pairs.
// R13: merged Q/K/V projection launch. R14: PV split-K (gridDim.z=2) + RED
// combine to fix single-wave triangular load imbalance.
// ---------------------------------------------------------------------------

constexpr int SEQ = 4096;
constexpr int DIM = 1024;

__device__ __half g_x2[2][(size_t)SEQ * DIM];
__device__ __half g_Wq2[2][(size_t)DIM * DIM];   // transposed [out][in]
__device__ __half g_Wk2[2][(size_t)DIM * DIM];
__device__ __half g_Wv2[2][(size_t)DIM * DIM];
__device__ __half g_Q2[2][(size_t)SEQ * DIM];
__device__ __half g_K2[2][(size_t)SEQ * DIM];
__device__ float  g_V[(size_t)SEQ * DIM];
__device__ __half g_Vt2[2][(size_t)DIM * SEQ];   // [dim][seq]
__device__ float  g_P[(size_t)SEQ * SEQ];        // logits
__device__ __half g_Ph[(size_t)SEQ * SEQ];       // fp16 unnormalized probs
__device__ float  g_rinv[SEQ];

// ---------------- helpers ---------------------------------------------------
__device__ __forceinline__ uint32_t smem_u32(const void* p) {
    uint32_t a;
    asm("{ .reg .u64 t; cvta.to.shared.u64 t, %1; cvt.u32.u64 %0, t; }"
        : "=r"(a) : "l"(p));
    return a;
}
__device__ __forceinline__ void cp16(uint32_t s, const void* g) {
    asm volatile("cp.async.cg.shared.global [%0], [%1], 16;" :: "r"(s), "l"(g));
}
#define CP_COMMIT() asm volatile("cp.async.commit_group;" ::: "memory")
#define CP_WAIT1()  asm volatile("cp.async.wait_group 1;" ::: "memory")
#define CP_WAIT0()  asm volatile("cp.async.wait_group 0;" ::: "memory")

__device__ __forceinline__ void ldsm4(uint32_t* r, uint32_t addr) {
    asm volatile("ldmatrix.sync.aligned.m8n8.x4.shared.b16 {%0,%1,%2,%3}, [%4];"
                 : "=r"(r[0]), "=r"(r[1]), "=r"(r[2]), "=r"(r[3]) : "r"(addr));
}
__device__ __forceinline__ void mma16816(float* d, const uint32_t* a, const uint32_t* b) {
    asm volatile(
        "mma.sync.aligned.m16n8k16.row.col.f32.f16.f16.f32 "
        "{%0,%1,%2,%3}, {%4,%5,%6,%7}, {%8,%9}, {%0,%1,%2,%3};"
        : "+f"(d[0]), "+f"(d[1]), "+f"(d[2]), "+f"(d[3])
        : "r"(a[0]), "r"(a[1]), "r"(a[2]), "r"(a[3]), "r"(b[0]), "r"(b[1]));
}

__device__ __forceinline__ void split2h(float v, __half& a, __half& b) {
    a = __float2half_rn(v);
    b = __float2half_rn(v - __half2float(a));
}

// ========== generic kernel — QK^T, PV (PV with SPLITK) =======================
template <int NA, int NB, int NPAIR, int EPI, bool KLIMF, bool COMPACT, bool SPLITK>
__global__ __launch_bounds__(256, 2)
void hmma_gemm(const __half* __restrict__ A0, const __half* __restrict__ A1,
               const __half* __restrict__ B0, const __half* __restrict__ B1,
               int lda, int ldb, int K,
               float* __restrict__ Cf,
               __half* __restrict__ O0, __half* __restrict__ O1,
               int ldc, const float* __restrict__ rinv)
{
    int bn, bm;
    if (COMPACT) {
        int t = blockIdx.x;
        bm = (int)((sqrtf(8.0f * t + 1.0f) - 1.0f) * 0.5f);
        while ((bm + 1) * (bm + 2) / 2 <= t) bm++;
        while (bm * (bm + 1) / 2 > t) bm--;
        bn = t - bm * (bm + 1) / 2;
    } else {
        bn = blockIdx.x; bm = blockIdx.y;
    }
    const int m0 = bm * 128, n0 = bn * 128;

    constexpr int NPL = NA + NB;
    constexpr uint32_t RSTR = 80;
    constexpr uint32_t PLSZ = 128 * RSTR;
    constexpr uint32_t STAGE = NPL * PLSZ;

    extern __shared__ char smem_dyn[];
    const uint32_t sbase = (smem_u32(smem_dyn) + 1023u) & ~1023u;

    const int tid  = threadIdx.x;
    const int lane = tid & 31;
    const int wid  = tid >> 5;
    const int wm   = (wid >> 2) * 64;
    const int wn   = (wid & 3) * 32;

    const __half* pl[NPL];
    pl[0] = A0; if (NA > 1) pl[1] = A1;
    pl[NA] = B0; if (NB > 1) pl[NA + 1] = B1;

    int Kend = K;
    if (KLIMF) { int kl = (bm + 1) * 128; Kend = kl < K ? kl : K; }
    const int nch = Kend >> 5;

    // split-K: z handles [c0, c1) of the chunk range (nch is a multiple of 4)
    int c0 = 0, c1 = nch;
    if (SPLITK) {
        const int half = nch >> 1;
        c0 = blockIdx.z * half;
        c1 = c0 + half;
    }

    auto load_stage = [&](int c, int buf) {
        const int k0 = c << 5;
        const uint32_t sb = sbase + buf * STAGE;
#pragma unroll
        for (int t = 0; t < NPL * 2; t++) {
            int idx = tid + t * 256;
            int plane = idx >> 9;
            int rem = idx & 511;
            int row = rem >> 2;
            int c4 = rem & 3;
            int rbase = (plane < NA) ? m0 : n0;
            int ld    = (plane < NA) ? lda : ldb;
            const __half* g = pl[plane] + (size_t)(rbase + row) * ld + k0 + c4 * 8;
            cp16(sb + plane * PLSZ + row * RSTR + c4 * 16, g);
        }
        CP_COMMIT();
    };

    float acc[4][4][4];
#pragma unroll
    for (int i = 0; i < 4; i++)
#pragma unroll
        for (int j = 0; j < 4; j++)
#pragma unroll
            for (int q = 0; q < 4; q++) acc[i][j][q] = 0.0f;

    constexpr int paA[3] = {0, 0, 1};
    constexpr int paB[3] = {0, 1, 0};

    load_stage(c0, 0);
    if (c0 + 1 < c1) load_stage(c0 + 1, 1);

    for (int c = c0; c < c1; c++) {
        if (c + 1 < c1) { CP_WAIT1(); } else { CP_WAIT0(); }
        __syncthreads();

        const uint32_t sb = sbase + ((c - c0) & 1) * STAGE;
        const uint32_t a_row = (uint32_t)(wm + (lane & 15));
        const uint32_t a_kb  = ((uint32_t)(lane >> 4)) << 4;
        const uint32_t b_row = (uint32_t)(wn + ((lane >> 1) & 8) + (lane & 7));
        const uint32_t b_kb  = ((uint32_t)((lane >> 3) & 1)) << 4;

#pragma unroll
        for (int k16 = 0; k16 < 2; k16++) {
            uint32_t bfr[NB][8];
#pragma unroll
            for (int p = 0; p < NB; p++) {
                const uint32_t pbn = sb + (NA + p) * PLSZ + k16 * 32 + b_kb;
#pragma unroll
                for (int nt2 = 0; nt2 < 2; nt2++)
                    ldsm4(&bfr[p][nt2 * 4], pbn + (b_row + nt2 * 16) * RSTR);
            }
#pragma unroll
            for (int ia = 0; ia < NA; ia++) {
                uint32_t af[4][4];
                const uint32_t pbm = sb + ia * PLSZ + k16 * 32 + a_kb;
#pragma unroll
                for (int mt = 0; mt < 4; mt++)
                    ldsm4(af[mt], pbm + (a_row + mt * 16) * RSTR);
#pragma unroll
                for (int p = 0; p < NPAIR; p++) {
                    if (paA[p] != ia) continue;
                    const int ib = paB[p];
#pragma unroll
                    for (int mt = 0; mt < 4; mt++)
#pragma unroll
                        for (int nt = 0; nt < 4; nt++)
                            mma16816(acc[mt][nt], af[mt], &bfr[ib][nt * 2]);
                }
            }
        }
        __syncthreads();
        if (c + 2 < c1) load_stage(c + 2, (c - c0) & 1);
    }

#pragma unroll
    for (int mt = 0; mt < 4; mt++) {
#pragma unroll
        for (int nt = 0; nt < 4; nt++) {
            const int gm = m0 + wm + mt * 16 + (lane >> 2);
            const int gn = n0 + wn + nt * 8 + (lane & 3) * 2;
            float c0v = acc[mt][nt][0], c1v = acc[mt][nt][1];
            float c2v = acc[mt][nt][2], c3v = acc[mt][nt][3];
            if (EPI == 0) {
                *reinterpret_cast<float2*>(&Cf[(size_t)gm * ldc + gn]) = make_float2(c0v, c1v);
                *reinterpret_cast<float2*>(&Cf[(size_t)(gm + 8) * ldc + gn]) = make_float2(c2v, c3v);
            } else if (EPI == 2) {
                float s0 = rinv[gm], s1 = rinv[gm + 8];
                if (SPLITK) {
                    atomicAdd(&Cf[(size_t)gm * ldc + gn],       c0v * s0);
                    atomicAdd(&Cf[(size_t)gm * ldc + gn + 1],   c1v * s0);
                    atomicAdd(&Cf[(size_t)(gm + 8) * ldc + gn],     c2v * s1);
                    atomicAdd(&Cf[(size_t)(gm + 8) * ldc + gn + 1], c3v * s1);
                } else {
                    *reinterpret_cast<float2*>(&Cf[(size_t)gm * ldc + gn]) =
                        make_float2(c0v * s0, c1v * s0);
                    *reinterpret_cast<float2*>(&Cf[(size_t)(gm + 8) * ldc + gn]) =
                        make_float2(c2v * s1, c3v * s1);
                }
            } else {
                __half a0, b0, a1, b1;
                __half2 t;
                split2h(c0v, a0, b0); split2h(c1v, a1, b1);
                t.x = a0; t.y = a1;
                *reinterpret_cast<__half2*>(&O0[(size_t)gm * ldc + gn]) = t;
                t.x = b0; t.y = b1;
                *reinterpret_cast<__half2*>(&O1[(size_t)gm * ldc + gn]) = t;
                split2h(c2v, a0, b0); split2h(c3v, a1, b1);
                t.x = a0; t.y = a1;
                *reinterpret_cast<__half2*>(&O0[(size_t)(gm + 8) * ldc + gn]) = t;
                t.x = b0; t.y = b1;
                *reinterpret_cast<__half2*>(&O1[(size_t)(gm + 8) * ldc + gn]) = t;
            }
        }
    }
}

// ========== merged Q/K/V projection (one launch, gridDim.z = 3) ==============
__global__ __launch_bounds__(256, 2)
void proj3_kernel(const __half* __restrict__ x0, const __half* __restrict__ x1,
                  const __half* __restrict__ Wq0, const __half* __restrict__ Wq1,
                  const __half* __restrict__ Wk0, const __half* __restrict__ Wk1,
                  const __half* __restrict__ Wv0, const __half* __restrict__ Wv1,
                  __half* __restrict__ Q0, __half* __restrict__ Q1,
                  __half* __restrict__ K0, __half* __restrict__ K1,
                  float* __restrict__ Vf)
{
    const int bn = blockIdx.x, bm = blockIdx.y, z = blockIdx.z;
    const int m0 = bm * 128, n0 = bn * 128;

    const __half* B0 = (z == 0) ? Wq0 : (z == 1) ? Wk0 : Wv0;
    const __half* B1 = (z == 0) ? Wq1 : (z == 1) ? Wk1 : Wv1;
    __half* O0 = (z == 0) ? Q0 : K0;
    __half* O1 = (z == 0) ? Q1 : K1;

    constexpr uint32_t RSTR = 80;
    constexpr uint32_t PLSZ = 128 * RSTR;
    constexpr uint32_t STAGE = 4 * PLSZ;

    extern __shared__ char smem_dyn[];
    const uint32_t sbase = (smem_u32(smem_dyn) + 1023u) & ~1023u;

    const int tid  = threadIdx.x;
    const int lane = tid & 31;
    const int wid  = tid >> 5;
    const int wm   = (wid >> 2) * 64;
    const int wn   = (wid & 3) * 32;

    const __half* pl[4] = {x0, x1, B0, B1};
    const int nch = DIM >> 5;   // 32

    auto load_stage = [&](int c, int buf) {
        const int k0 = c << 5;
        const uint32_t sb = sbase + buf * STAGE;
#pragma unroll
        for (int t = 0; t < 8; t++) {
            int idx = tid + t * 256;
            int plane = idx >> 9;
            int rem = idx & 511;
            int row = rem >> 2;
            int c4 = rem & 3;
            int rbase = (plane < 2) ? m0 : n0;
            const __half* g = pl[plane] + (size_t)(rbase + row) * DIM + k0 + c4 * 8;
            cp16(sb + plane * PLSZ + row * RSTR + c4 * 16, g);
        }
        CP_COMMIT();
    };

    float acc[4][4][4];
#pragma unroll
    for (int i = 0; i < 4; i++)
#pragma unroll
        for (int j = 0; j < 4; j++)
#pragma unroll
            for (int q = 0; q < 4; q++) acc[i][j][q] = 0.0f;

    load_stage(0, 0);
    load_stage(1, 1);

    for (int c = 0; c < nch; c++) {
        if (c + 1 < nch) { CP_WAIT1(); } else { CP_WAIT0(); }
        __syncthreads();

        const uint32_t sb = sbase + (c & 1) * STAGE;
        const uint32_t a_row = (uint32_t)(wm + (lane & 15));
        const uint32_t a_kb  = ((uint32_t)(lane >> 4)) << 4;
        const uint32_t b_row = (uint32_t)(wn + ((lane >> 1) & 8) + (lane & 7));
        const uint32_t b_kb  = ((uint32_t)((lane >> 3) & 1)) << 4;

#pragma unroll
        for (int k16 = 0; k16 < 2; k16++) {
            uint32_t bfr[2][8];
#pragma unroll
            for (int p = 0; p < 2; p++) {
                const uint32_t pbn = sb + (2 + p) * PLSZ + k16 * 32 + b_kb;
#pragma unroll
                for (int nt2 = 0; nt2 < 2; nt2++)
                    ldsm4(&bfr[p][nt2 * 4], pbn + (b_row + nt2 * 16) * RSTR);
            }
            {
                uint32_t af[4][4];
                const uint32_t pbm = sb + k16 * 32 + a_kb;
#pragma unroll
                for (int mt = 0; mt < 4; mt++)
                    ldsm4(af[mt], pbm + (a_row + mt * 16) * RSTR);
#pragma unroll
                for (int ib = 0; ib < 2; ib++)
#pragma unroll
                    for (int mt = 0; mt < 4; mt++)
#pragma unroll
                        for (int nt = 0; nt < 4; nt++)
                            mma16816(acc[mt][nt], af[mt], &bfr[ib][nt * 2]);
            }
            if (z < 2) {
                uint32_t af[4][4];
                const uint32_t pbm = sb + PLSZ + k16 * 32 + a_kb;
#pragma unroll
                for (int mt = 0; mt < 4; mt++)
                    ldsm4(af[mt], pbm + (a_row + mt * 16) * RSTR);
#pragma unroll
                for (int mt = 0; mt < 4; mt++)
#pragma unroll
                    for (int nt = 0; nt < 4; nt++)
                        mma16816(acc[mt][nt], af[mt], &bfr[0][nt * 2]);
            }
        }
        __syncthreads();
        if (c + 2 < nch) load_stage(c + 2, c & 1);
    }

#pragma unroll
    for (int mt = 0; mt < 4; mt++) {
#pragma unroll
        for (int nt = 0; nt < 4; nt++) {
            const int gm = m0 + wm + mt * 16 + (lane >> 2);
            const int gn = n0 + wn + nt * 8 + (lane & 3) * 2;
            float c0 = acc[mt][nt][0], c1 = acc[mt][nt][1];
            float c2 = acc[mt][nt][2], c3 = acc[mt][nt][3];
            if (z == 2) {
                *reinterpret_cast<float2*>(&Vf[(size_t)gm * DIM + gn]) = make_float2(c0, c1);
                *reinterpret_cast<float2*>(&Vf[(size_t)(gm + 8) * DIM + gn]) = make_float2(c2, c3);
            } else {
                __half a0, b0, a1, b1;
                __half2 t;
                split2h(c0, a0, b0); split2h(c1, a1, b1);
                t.x = a0; t.y = a1;
                *reinterpret_cast<__half2*>(&O0[(size_t)gm * DIM + gn]) = t;
                t.x = b0; t.y = b1;
                *reinterpret_cast<__half2*>(&O1[(size_t)gm * DIM + gn]) = t;
                split2h(c2, a0, b0); split2h(c3, a1, b1);
                t.x = a0; t.y = a1;
                *reinterpret_cast<__half2*>(&O0[(size_t)(gm + 8) * DIM + gn]) = t;
                t.x = b0; t.y = b1;
                *reinterpret_cast<__half2*>(&O1[(size_t)(gm + 8) * DIM + gn]) = t;
            }
        }
    }
}

// ---------------- prep kernels ----------------------------------------------
__global__ void split2_kernel(const float* __restrict__ in, size_t n,
                              __half* __restrict__ o0, __half* __restrict__ o1)
{
    size_t i = (size_t)blockIdx.x * blockDim.x + threadIdx.x;
    size_t stride = (size_t)gridDim.x * blockDim.x;
    for (; i < n; i += stride) {
        __half a, b;
        split2h(in[i], a, b);
        o0[i] = a; o1[i] = b;
    }
}

__global__ void tsplitW_kernel(const float* __restrict__ Wq, const float* __restrict__ Wk,
                               const float* __restrict__ Wv,
                               __half* __restrict__ q0, __half* __restrict__ q1,
                               __half* __restrict__ k0, __half* __restrict__ k1,
                               __half* __restrict__ v0, __half* __restrict__ v1)
{
    const float* in = (blockIdx.z == 0) ? Wq : (blockIdx.z == 1) ? Wk : Wv;
    __half* o0 = (blockIdx.z == 0) ? q0 : (blockIdx.z == 1) ? k0 : v0;
    __half* o1 = (blockIdx.z == 0) ? q1 : (blockIdx.z == 1) ? k1 : v1;
    __shared__ float t[32][33];
    const int bc = blockIdx.x * 32, br = blockIdx.y * 32;
    const int tx = threadIdx.x, ty = threadIdx.y;
#pragma unroll
    for (int i = 0; i < 4; i++)
        t[ty + i * 8][tx] = in[(size_t)(br + ty + i * 8) * DIM + bc + tx];
    __syncthreads();
#pragma unroll
    for (int i = 0; i < 4; i++) {
        float v = t[tx][ty + i * 8];
        size_t o = (size_t)(bc + ty + i * 8) * DIM + br + tx;
        __half a, b;
        split2h(v, a, b);
        o0[o] = a; o1[o] = b;
    }
}

__global__ void tsplitV_kernel(const float* __restrict__ in,
                               __half* __restrict__ o0, __half* __restrict__ o1)
{
    __shared__ float t[32][33];
    const int bc = blockIdx.x * 32, br = blockIdx.y * 32;
    const int tx = threadIdx.x, ty = threadIdx.y;
#pragma unroll
    for (int i = 0; i < 4; i++)
        t[ty + i * 8][tx] = in[(size_t)(br + ty + i * 8) * DIM + bc + tx];
    __syncthreads();
#pragma unroll
    for (int i = 0; i < 4; i++) {
        float v = t[tx][ty + i * 8];
        size_t o = (size_t)(bc + ty + i * 8) * SEQ + br + tx;
        __half a, b;
        split2h(v, a, b);
        o0[o] = a; o1[o] = b;
    }
}

__global__ __launch_bounds__(256)
void softmax_h(const float* __restrict__ P, __half* __restrict__ Ph,
               float* __restrict__ rinv)
{
    const int row   = blockIdx.x;
    const int valid = row + 1;
    const int klim  = ((row >> 7) + 1) << 7;
    const float* prow = P + (size_t)row * SEQ;
    const int tid = threadIdx.x;
    __shared__ float red[256];

    float m = -3.402823466e38f;
    for (int j = tid; j < valid; j += 256) m = fmaxf(m, prow[j]);
    red[tid] = m;
    __syncthreads();
#pragma unroll
    for (int s = 128; s > 0; s >>= 1) {
        if (tid < s) red[tid] = fmaxf(red[tid], red[tid + s]);
        __syncthreads();
    }
    m = red[0];
    __syncthreads();

    const float inv_sqrt_d = 0.03125f;
    float sum = 0.0f;
    for (int j = tid; j < klim; j += 256) {
        float e = 0.0f;
        if (j < valid) e = __expf((prow[j] - m) * inv_sqrt_d);
        __half h = __float2half_rn(e);
        Ph[(size_t)row * SEQ + j] = h;
        sum += __half2float(h);
    }
    red[tid] = sum;
    __syncthreads();
#pragma unroll
    for (int s = 128; s > 0; s >>= 1) {
        if (tid < s) red[tid] += red[tid + s];
        __syncthreads();
    }
    if (tid == 0) rinv[row] = 1.0f / red[0];
}

// ---------------- host side --------------------------------------------------
extern "C" void kernel_launch(void* const* d_in, const int* in_sizes, int n_in,
                              void* d_out, int out_size)
{
    const float* x  = (const float*)d_in[0];
    const float* Wq = (const float*)d_in[1];
    const float* Wk = (const float*)d_in[2];
    const float* Wv = (const float*)d_in[3];
    float* out = (float*)d_out;

    __half *x2[2], *Wq2[2], *Wk2[2], *Wv2[2], *Q2[2], *K2[2], *Vt2[2];
    __half *Ph;
    float *V, *P, *rinv;
    for (int i = 0; i < 2; i++) {
        cudaGetSymbolAddress((void**)&x2[i],  g_x2);  x2[i]  += (size_t)i * SEQ * DIM;
        cudaGetSymbolAddress((void**)&Wq2[i], g_Wq2); Wq2[i] += (size_t)i * DIM * DIM;
        cudaGetSymbolAddress((void**)&Wk2[i], g_Wk2); Wk2[i] += (size_t)i * DIM * DIM;
        cudaGetSymbolAddress((void**)&Wv2[i], g_Wv2); Wv2[i] += (size_t)i * DIM * DIM;
        cudaGetSymbolAddress((void**)&Q2[i],  g_Q2);  Q2[i]  += (size_t)i * SEQ * DIM;
        cudaGetSymbolAddress((void**)&K2[i],  g_K2);  K2[i]  += (size_t)i * SEQ * DIM;
        cudaGetSymbolAddress((void**)&Vt2[i], g_Vt2); Vt2[i] += (size_t)i * DIM * SEQ;
    }
    cudaGetSymbolAddress((void**)&Ph,   g_Ph);
    cudaGetSymbolAddress((void**)&V,    g_V);
    cudaGetSymbolAddress((void**)&P,    g_P);
    cudaGetSymbolAddress((void**)&rinv, g_rinv);

    auto gemm_causal = hmma_gemm<2, 2, 3, 0, false, true,  false>;  // QK^T (compact)
    auto gemm_pv     = hmma_gemm<1, 2, 2, 2, true,  false, true>;   // PV split-K

    const int SM4 = 2 * 4 * 10240 + 1024;   // 82944
    const int SM3 = 2 * 3 * 10240 + 1024;   // 62464
    cudaFuncSetAttribute(proj3_kernel, cudaFuncAttributeMaxDynamicSharedMemorySize, SM4);
    cudaFuncSetAttribute(gemm_causal,  cudaFuncAttributeMaxDynamicSharedMemorySize, SM4);
    cudaFuncSetAttribute(gemm_pv,      cudaFuncAttributeMaxDynamicSharedMemorySize, SM3);

    // 1) operand splits
    split2_kernel<<<1024, 256>>>(x, (size_t)SEQ * DIM, x2[0], x2[1]);
    dim3 tb(32, 8);
    tsplitW_kernel<<<dim3(DIM / 32, DIM / 32, 3), tb>>>(Wq, Wk, Wv,
                                                        Wq2[0], Wq2[1], Wk2[0], Wk2[1],
                                                        Wv2[0], Wv2[1]);

    // 2) all three projections in ONE launch (768 CTAs)
    proj3_kernel<<<dim3(DIM / 128, SEQ / 128, 3), 256, SM4>>>(
        x2[0], x2[1], Wq2[0], Wq2[1], Wk2[0], Wk2[1], Wv2[0], Wv2[1],
        Q2[0], Q2[1], K2[0], K2[1], V);

    // 3) V -> Vt (split2, transposed)
    tsplitV_kernel<<<dim3(DIM / 32, SEQ / 32), tb>>>(V, Vt2[0], Vt2[1]);

    // 4) logits: compact lower-triangular grid (528 CTAs)
    gemm_causal<<<dim3(32 * 33 / 2), 256, SM4>>>(Q2[0], Q2[1], K2[0], K2[1],
                                                 DIM, DIM, DIM, P, nullptr, nullptr, SEQ, nullptr);

    // 5) softmax -> fp16 probs + rinv of rounded sum
    softmax_h<<<SEQ, 256>>>(P, Ph, rinv);

    // 6) out = (Ph @ V) * rinv, split-K over 2 CTAs per tile (RED combine)
    cudaMemsetAsync(out, 0, (size_t)SEQ * DIM * sizeof(float));
    gemm_pv<<<dim3(DIM / 128, SEQ / 128, 2), 256, SM3>>>(Ph, nullptr, Vt2[0], Vt2[1],
                                                         SEQ, SEQ, SEQ, out, nullptr, nullptr,
                                                         DIM, rinv);
}

// round 15
// speedup vs baseline: 1.0996x; 1.0013x over previous
#include <cuda_runtime.h>
#include <cuda_fp16.h>
#include <cstdint>

// ---------------------------------------------------------------------------
// SelfAttention via mma.sync (HMMA) fp16-emulated-fp32 GEMMs.
// fp32 operand = hi + lo fp16 planes; 3 pair-products (hh,hl,lh) ~2^-22.
// V proj: x_hi @ (Wv_hi + Wv_lo), 2 pairs. PV: fp16 P (rounded-sum norm), 2 pairs.
// R13: merged QKV proj. R14: PV split-K. R15: QK^T epilogue computes row maxes
// (atomicMax, order-independent) -> single-pass softmax.
// ---------------------------------------------------------------------------

constexpr int SEQ = 4096;
constexpr int DIM = 1024;

__device__ __half g_x2[2][(size_t)SEQ * DIM];
__device__ __half g_Wq2[2][(size_t)DIM * DIM];   // transposed [out][in]
__device__ __half g_Wk2[2][(size_t)DIM * DIM];
__device__ __half g_Wv2[2][(size_t)DIM * DIM];
__device__ __half g_Q2[2][(size_t)SEQ * DIM];
__device__ __half g_K2[2][(size_t)SEQ * DIM];
__device__ float  g_V[(size_t)SEQ * DIM];
__device__ __half g_Vt2[2][(size_t)DIM * SEQ];   // [dim][seq]
__device__ float  g_P[(size_t)SEQ * SEQ];        // scaled logits
__device__ __half g_Ph[(size_t)SEQ * SEQ];       // fp16 unnormalized probs
__device__ float  g_rinv[SEQ];
__device__ float  g_rowmax[SEQ];

// ---------------- helpers ---------------------------------------------------
__device__ __forceinline__ uint32_t smem_u32(const void* p) {
    uint32_t a;
    asm("{ .reg .u64 t; cvta.to.shared.u64 t, %1; cvt.u32.u64 %0, t; }"
        : "=r"(a) : "l"(p));
    return a;
}
__device__ __forceinline__ void cp16(uint32_t s, const void* g) {
    asm volatile("cp.async.cg.shared.global [%0], [%1], 16;" :: "r"(s), "l"(g));
}
#define CP_COMMIT() asm volatile("cp.async.commit_group;" ::: "memory")
#define CP_WAIT1()  asm volatile("cp.async.wait_group 1;" ::: "memory")
#define CP_WAIT0()  asm volatile("cp.async.wait_group 0;" ::: "memory")

__device__ __forceinline__ void ldsm4(uint32_t* r, uint32_t addr) {
    asm volatile("ldmatrix.sync.aligned.m8n8.x4.shared.b16 {%0,%1,%2,%3}, [%4];"
                 : "=r"(r[0]), "=r"(r[1]), "=r"(r[2]), "=r"(r[3]) : "r"(addr));
}
__device__ __forceinline__ void mma16816(float* d, const uint32_t* a, const uint32_t* b) {
    asm volatile(
        "mma.sync.aligned.m16n8k16.row.col.f32.f16.f16.f32 "
        "{%0,%1,%2,%3}, {%4,%5,%6,%7}, {%8,%9}, {%0,%1,%2,%3};"
        : "+f"(d[0]), "+f"(d[1]), "+f"(d[2]), "+f"(d[3])
        : "r"(a[0]), "r"(a[1]), "r"(a[2]), "r"(a[3]), "r"(b[0]), "r"(b[1]));
}

__device__ __forceinline__ void split2h(float v, __half& a, __half& b) {
    a = __float2half_rn(v);
    b = __float2half_rn(v - __half2float(a));
}
// order-independent float atomic max (monotone int/uint encoding)
__device__ __forceinline__ void atomicMaxF(float* a, float v) {
    if (v >= 0.0f) atomicMax((int*)a, __float_as_int(v));
    else           atomicMin((unsigned int*)a, (unsigned int)__float_as_int(v));
}

// ========== generic kernel — QK^T (EPI=3 rowmax), PV (SPLITK) ================
// EPI: 0 = f32 C; 2 = f32 * rinv[row] (atomic when SPLITK);
//      3 = scaled f32 C + atomic row-max (causal-masked on diagonal blocks)
template <int NA, int NB, int NPAIR, int EPI, bool KLIMF, bool COMPACT, bool SPLITK>
__global__ __launch_bounds__(256, 2)
void hmma_gemm(const __half* __restrict__ A0, const __half* __restrict__ A1,
               const __half* __restrict__ B0, const __half* __restrict__ B1,
               int lda, int ldb, int K,
               float* __restrict__ Cf,
               __half* __restrict__ O0, __half* __restrict__ O1,
               int ldc, const float* __restrict__ rinv,
               float* __restrict__ rowmax)
{
    int bn, bm;
    if (COMPACT) {
        int t = blockIdx.x;
        bm = (int)((sqrtf(8.0f * t + 1.0f) - 1.0f) * 0.5f);
        while ((bm + 1) * (bm + 2) / 2 <= t) bm++;
        while (bm * (bm + 1) / 2 > t) bm--;
        bn = t - bm * (bm + 1) / 2;
    } else {
        bn = blockIdx.x; bm = blockIdx.y;
    }
    const int m0 = bm * 128, n0 = bn * 128;
    const bool diag = COMPACT && (bm == bn);

    constexpr int NPL = NA + NB;
    constexpr uint32_t RSTR = 80;
    constexpr uint32_t PLSZ = 128 * RSTR;
    constexpr uint32_t STAGE = NPL * PLSZ;

    extern __shared__ char smem_dyn[];
    const uint32_t sbase = (smem_u32(smem_dyn) + 1023u) & ~1023u;

    const int tid  = threadIdx.x;
    const int lane = tid & 31;
    const int wid  = tid >> 5;
    const int wm   = (wid >> 2) * 64;
    const int wn   = (wid & 3) * 32;

    const __half* pl[NPL];
    pl[0] = A0; if (NA > 1) pl[1] = A1;
    pl[NA] = B0; if (NB > 1) pl[NA + 1] = B1;

    int Kend = K;
    if (KLIMF) { int kl = (bm + 1) * 128; Kend = kl < K ? kl : K; }
    const int nch = Kend >> 5;

    int c0 = 0, c1 = nch;
    if (SPLITK) {
        const int half = nch >> 1;
        c0 = blockIdx.z * half;
        c1 = c0 + half;
    }

    auto load_stage = [&](int c, int buf) {
        const int k0 = c << 5;
        const uint32_t sb = sbase + buf * STAGE;
#pragma unroll
        for (int t = 0; t < NPL * 2; t++) {
            int idx = tid + t * 256;
            int plane = idx >> 9;
            int rem = idx & 511;
            int row = rem >> 2;
            int c4 = rem & 3;
            int rbase = (plane < NA) ? m0 : n0;
            int ld    = (plane < NA) ? lda : ldb;
            const __half* g = pl[plane] + (size_t)(rbase + row) * ld + k0 + c4 * 8;
            cp16(sb + plane * PLSZ + row * RSTR + c4 * 16, g);
        }
        CP_COMMIT();
    };

    float acc[4][4][4];
#pragma unroll
    for (int i = 0; i < 4; i++)
#pragma unroll
        for (int j = 0; j < 4; j++)
#pragma unroll
            for (int q = 0; q < 4; q++) acc[i][j][q] = 0.0f;

    constexpr int paA[3] = {0, 0, 1};
    constexpr int paB[3] = {0, 1, 0};

    load_stage(c0, 0);
    if (c0 + 1 < c1) load_stage(c0 + 1, 1);

    for (int c = c0; c < c1; c++) {
        if (c + 1 < c1) { CP_WAIT1(); } else { CP_WAIT0(); }
        __syncthreads();

        const uint32_t sb = sbase + ((c - c0) & 1) * STAGE;
        const uint32_t a_row = (uint32_t)(wm + (lane & 15));
        const uint32_t a_kb  = ((uint32_t)(lane >> 4)) << 4;
        const uint32_t b_row = (uint32_t)(wn + ((lane >> 1) & 8) + (lane & 7));
        const uint32_t b_kb  = ((uint32_t)((lane >> 3) & 1)) << 4;

#pragma unroll
        for (int k16 = 0; k16 < 2; k16++) {
            uint32_t bfr[NB][8];
#pragma unroll
            for (int p = 0; p < NB; p++) {
                const uint32_t pbn = sb + (NA + p) * PLSZ + k16 * 32 + b_kb;
#pragma unroll
                for (int nt2 = 0; nt2 < 2; nt2++)
                    ldsm4(&bfr[p][nt2 * 4], pbn + (b_row + nt2 * 16) * RSTR);
            }
#pragma unroll
            for (int ia = 0; ia < NA; ia++) {
                uint32_t af[4][4];
                const uint32_t pbm = sb + ia * PLSZ + k16 * 32 + a_kb;
#pragma unroll
                for (int mt = 0; mt < 4; mt++)
                    ldsm4(af[mt], pbm + (a_row + mt * 16) * RSTR);
#pragma unroll
                for (int p = 0; p < NPAIR; p++) {
                    if (paA[p] != ia) continue;
                    const int ib = paB[p];
#pragma unroll
                    for (int mt = 0; mt < 4; mt++)
#pragma unroll
                        for (int nt = 0; nt < 4; nt++)
                            mma16816(acc[mt][nt], af[mt], &bfr[ib][nt * 2]);
                }
            }
        }
        __syncthreads();
        if (c + 2 < c1) load_stage(c + 2, (c - c0) & 1);
    }

    // ---------------- epilogue ----------------------------------------------
    const float lscale = 0.03125f;   // 1/sqrt(1024)
#pragma unroll
    for (int mt = 0; mt < 4; mt++) {
        const int gm = m0 + wm + mt * 16 + (lane >> 2);
        float m0r = -3.402823466e38f, m1r = -3.402823466e38f;
#pragma unroll
        for (int nt = 0; nt < 4; nt++) {
            const int gn = n0 + wn + nt * 8 + (lane & 3) * 2;
            float c0v = acc[mt][nt][0], c1v = acc[mt][nt][1];
            float c2v = acc[mt][nt][2], c3v = acc[mt][nt][3];
            if (EPI == 0) {
                *reinterpret_cast<float2*>(&Cf[(size_t)gm * ldc + gn]) = make_float2(c0v, c1v);
                *reinterpret_cast<float2*>(&Cf[(size_t)(gm + 8) * ldc + gn]) = make_float2(c2v, c3v);
            } else if (EPI == 3) {
                c0v *= lscale; c1v *= lscale; c2v *= lscale; c3v *= lscale;
                *reinterpret_cast<float2*>(&Cf[(size_t)gm * ldc + gn]) = make_float2(c0v, c1v);
                *reinterpret_cast<float2*>(&Cf[(size_t)(gm + 8) * ldc + gn]) = make_float2(c2v, c3v);
                if (!diag || gn     <= gm)     m0r = fmaxf(m0r, c0v);
                if (!diag || gn + 1 <= gm)     m0r = fmaxf(m0r, c1v);
                if (!diag || gn     <= gm + 8) m1r = fmaxf(m1r, c2v);
                if (!diag || gn + 1 <= gm + 8) m1r = fmaxf(m1r, c3v);
            } else if (EPI == 2) {
                float s0 = rinv[gm], s1 = rinv[gm + 8];
                if (SPLITK) {
                    atomicAdd(&Cf[(size_t)gm * ldc + gn],       c0v * s0);
                    atomicAdd(&Cf[(size_t)gm * ldc + gn + 1],   c1v * s0);
                    atomicAdd(&Cf[(size_t)(gm + 8) * ldc + gn],     c2v * s1);
                    atomicAdd(&Cf[(size_t)(gm + 8) * ldc + gn + 1], c3v * s1);
                } else {
                    *reinterpret_cast<float2*>(&Cf[(size_t)gm * ldc + gn]) =
                        make_float2(c0v * s0, c1v * s0);
                    *reinterpret_cast<float2*>(&Cf[(size_t)(gm + 8) * ldc + gn]) =
                        make_float2(c2v * s1, c3v * s1);
                }
            }
        }
        if (EPI == 3) {
            m0r = fmaxf(m0r, __shfl_xor_sync(0xffffffffu, m0r, 1));
            m0r = fmaxf(m0r, __shfl_xor_sync(0xffffffffu, m0r, 2));
            m1r = fmaxf(m1r, __shfl_xor_sync(0xffffffffu, m1r, 1));
            m1r = fmaxf(m1r, __shfl_xor_sync(0xffffffffu, m1r, 2));
            if ((lane & 3) == 0) {
                atomicMaxF(&rowmax[gm], m0r);
                atomicMaxF(&rowmax[gm + 8], m1r);
            }
        }
    }
}

// ========== merged Q/K/V projection (one launch, gridDim.z = 3) ==============
__global__ __launch_bounds__(256, 2)
void proj3_kernel(const __half* __restrict__ x0, const __half* __restrict__ x1,
                  const __half* __restrict__ Wq0, const __half* __restrict__ Wq1,
                  const __half* __restrict__ Wk0, const __half* __restrict__ Wk1,
                  const __half* __restrict__ Wv0, const __half* __restrict__ Wv1,
                  __half* __restrict__ Q0, __half* __restrict__ Q1,
                  __half* __restrict__ K0, __half* __restrict__ K1,
                  float* __restrict__ Vf)
{
    const int bn = blockIdx.x, bm = blockIdx.y, z = blockIdx.z;
    const int m0 = bm * 128, n0 = bn * 128;

    const __half* B0 = (z == 0) ? Wq0 : (z == 1) ? Wk0 : Wv0;
    const __half* B1 = (z == 0) ? Wq1 : (z == 1) ? Wk1 : Wv1;
    __half* O0 = (z == 0) ? Q0 : K0;
    __half* O1 = (z == 0) ? Q1 : K1;

    constexpr uint32_t RSTR = 80;
    constexpr uint32_t PLSZ = 128 * RSTR;
    constexpr uint32_t STAGE = 4 * PLSZ;

    extern __shared__ char smem_dyn[];
    const uint32_t sbase = (smem_u32(smem_dyn) + 1023u) & ~1023u;

    const int tid  = threadIdx.x;
    const int lane = tid & 31;
    const int wid  = tid >> 5;
    const int wm   = (wid >> 2) * 64;
    const int wn   = (wid & 3) * 32;

    const __half* pl[4] = {x0, x1, B0, B1};
    const int nch = DIM >> 5;   // 32

    auto load_stage = [&](int c, int buf) {
        const int k0 = c << 5;
        const uint32_t sb = sbase + buf * STAGE;
#pragma unroll
        for (int t = 0; t < 8; t++) {
            int idx = tid + t * 256;
            int plane = idx >> 9;
            int rem = idx & 511;
            int row = rem >> 2;
            int c4 = rem & 3;
            int rbase = (plane < 2) ? m0 : n0;
            const __half* g = pl[plane] + (size_t)(rbase + row) * DIM + k0 + c4 * 8;
            cp16(sb + plane * PLSZ + row * RSTR + c4 * 16, g);
        }
        CP_COMMIT();
    };

    float acc[4][4][4];
#pragma unroll
    for (int i = 0; i < 4; i++)
#pragma unroll
        for (int j = 0; j < 4; j++)
#pragma unroll
            for (int q = 0; q < 4; q++) acc[i][j][q] = 0.0f;

    load_stage(0, 0);
    load_stage(1, 1);

    for (int c = 0; c < nch; c++) {
        if (c + 1 < nch) { CP_WAIT1(); } else { CP_WAIT0(); }
        __syncthreads();

        const uint32_t sb = sbase + (c & 1) * STAGE;
        const uint32_t a_row = (uint32_t)(wm + (lane & 15));
        const uint32_t a_kb  = ((uint32_t)(lane >> 4)) << 4;
        const uint32_t b_row = (uint32_t)(wn + ((lane >> 1) & 8) + (lane & 7));
        const uint32_t b_kb  = ((uint32_t)((lane >> 3) & 1)) << 4;

#pragma unroll
        for (int k16 = 0; k16 < 2; k16++) {
            uint32_t bfr[2][8];
#pragma unroll
            for (int p = 0; p < 2; p++) {
                const uint32_t pbn = sb + (2 + p) * PLSZ + k16 * 32 + b_kb;
#pragma unroll
                for (int nt2 = 0; nt2 < 2; nt2++)
                    ldsm4(&bfr[p][nt2 * 4], pbn + (b_row + nt2 * 16) * RSTR);
            }
            {
                uint32_t af[4][4];
                const uint32_t pbm = sb + k16 * 32 + a_kb;
#pragma unroll
                for (int mt = 0; mt < 4; mt++)
                    ldsm4(af[mt], pbm + (a_row + mt * 16) * RSTR);
#pragma unroll
                for (int ib = 0; ib < 2; ib++)
#pragma unroll
                    for (int mt = 0; mt < 4; mt++)
#pragma unroll
                        for (int nt = 0; nt < 4; nt++)
                            mma16816(acc[mt][nt], af[mt], &bfr[ib][nt * 2]);
            }
            if (z < 2) {
                uint32_t af[4][4];
                const uint32_t pbm = sb + PLSZ + k16 * 32 + a_kb;
#pragma unroll
                for (int mt = 0; mt < 4; mt++)
                    ldsm4(af[mt], pbm + (a_row + mt * 16) * RSTR);
#pragma unroll
                for (int mt = 0; mt < 4; mt++)
#pragma unroll
                    for (int nt = 0; nt < 4; nt++)
                        mma16816(acc[mt][nt], af[mt], &bfr[0][nt * 2]);
            }
        }
        __syncthreads();
        if (c + 2 < nch) load_stage(c + 2, c & 1);
    }

#pragma unroll
    for (int mt = 0; mt < 4; mt++) {
#pragma unroll
        for (int nt = 0; nt < 4; nt++) {
            const int gm = m0 + wm + mt * 16 + (lane >> 2);
            const int gn = n0 + wn + nt * 8 + (lane & 3) * 2;
            float c0 = acc[mt][nt][0], c1 = acc[mt][nt][1];
            float c2 = acc[mt][nt][2], c3 = acc[mt][nt][3];
            if (z == 2) {
                *reinterpret_cast<float2*>(&Vf[(size_t)gm * DIM + gn]) = make_float2(c0, c1);
                *reinterpret_cast<float2*>(&Vf[(size_t)(gm + 8) * DIM + gn]) = make_float2(c2, c3);
            } else {
                __half a0, b0, a1, b1;
                __half2 t;
                split2h(c0, a0, b0); split2h(c1, a1, b1);
                t.x = a0; t.y = a1;
                *reinterpret_cast<__half2*>(&O0[(size_t)gm * DIM + gn]) = t;
                t.x = b0; t.y = b1;
                *reinterpret_cast<__half2*>(&O1[(size_t)gm * DIM + gn]) = t;
                split2h(c2, a0, b0); split2h(c3, a1, b1);
                t.x = a0; t.y = a1;
                *reinterpret_cast<__half2*>(&O0[(size_t)(gm + 8) * DIM + gn]) = t;
                t.x = b0; t.y = b1;
                *reinterpret_cast<__half2*>(&O1[(size_t)(gm + 8) * DIM + gn]) = t;
            }
        }
    }
}

// ---------------- prep kernels ----------------------------------------------
__global__ void split2_kernel(const float* __restrict__ in, size_t n,
                              __half* __restrict__ o0, __half* __restrict__ o1,
                              float* __restrict__ rowmax)
{
    size_t i = (size_t)blockIdx.x * blockDim.x + threadIdx.x;
    if (i < SEQ) rowmax[i] = __int_as_float(0xFF800000);   // -inf, per-launch reset
    size_t stride = (size_t)gridDim.x * blockDim.x;
    for (; i < n; i += stride) {
        __half a, b;
        split2h(in[i], a, b);
        o0[i] = a; o1[i] = b;
    }
}

__global__ void tsplitW_kernel(const float* __restrict__ Wq, const float* __restrict__ Wk,
                               const float* __restrict__ Wv,
                               __half* __restrict__ q0, __half* __restrict__ q1,
                               __half* __restrict__ k0, __half* __restrict__ k1,
                               __half* __restrict__ v0, __half* __restrict__ v1)
{
    const float* in = (blockIdx.z == 0) ? Wq : (blockIdx.z == 1) ? Wk : Wv;
    __half* o0 = (blockIdx.z == 0) ? q0 : (blockIdx.z == 1) ? k0 : v0;
    __half* o1 = (blockIdx.z == 0) ? q1 : (blockIdx.z == 1) ? k1 : v1;
    __shared__ float t[32][33];
    const int bc = blockIdx.x * 32, br = blockIdx.y * 32;
    const int tx = threadIdx.x, ty = threadIdx.y;
#pragma unroll
    for (int i = 0; i < 4; i++)
        t[ty + i * 8][tx] = in[(size_t)(br + ty + i * 8) * DIM + bc + tx];
    __syncthreads();
#pragma unroll
    for (int i = 0; i < 4; i++) {
        float v = t[tx][ty + i * 8];
        size_t o = (size_t)(bc + ty + i * 8) * DIM + br + tx;
        __half a, b;
        split2h(v, a, b);
        o0[o] = a; o1[o] = b;
    }
}

__global__ void tsplitV_kernel(const float* __restrict__ in,
                               __half* __restrict__ o0, __half* __restrict__ o1)
{
    __shared__ float t[32][33];
    const int bc = blockIdx.x * 32, br = blockIdx.y * 32;
    const int tx = threadIdx.x, ty = threadIdx.y;
#pragma unroll
    for (int i = 0; i < 4; i++)
        t[ty + i * 8][tx] = in[(size_t)(br + ty + i * 8) * DIM + bc + tx];
    __syncthreads();
#pragma unroll
    for (int i = 0; i < 4; i++) {
        float v = t[tx][ty + i * 8];
        size_t o = (size_t)(bc + ty + i * 8) * SEQ + br + tx;
        __half a, b;
        split2h(v, a, b);
        o0[o] = a; o1[o] = b;
    }
}

// single-pass softmax: logits pre-scaled, row max precomputed by QK^T epilogue
__global__ __launch_bounds__(256)
void softmax_h(const float* __restrict__ P, const float* __restrict__ rowmax,
               __half* __restrict__ Ph, float* __restrict__ rinv)
{
    const int row   = blockIdx.x;
    const int valid = row + 1;
    const int klim  = ((row >> 7) + 1) << 7;
    const float* prow = P + (size_t)row * SEQ;
    const int tid = threadIdx.x;
    __shared__ float red[256];

    const float m = rowmax[row];
    float sum = 0.0f;
    for (int j = tid; j < klim; j += 256) {
        float e = 0.0f;
        if (j < valid) e = __expf(prow[j] - m);
        __half h = __float2half_rn(e);
        Ph[(size_t)row * SEQ + j] = h;
        sum += __half2float(h);
    }
    red[tid] = sum;
    __syncthreads();
#pragma unroll
    for (int s = 128; s > 0; s >>= 1) {
        if (tid < s) red[tid] += red[tid + s];
        __syncthreads();
    }
    if (tid == 0) rinv[row] = 1.0f / red[0];
}

// ---------------- host side --------------------------------------------------
extern "C" void kernel_launch(void* const* d_in, const int* in_sizes, int n_in,
                              void* d_out, int out_size)
{
    const float* x  = (const float*)d_in[0];
    const float* Wq = (const float*)d_in[1];
    const float* Wk = (const float*)d_in[2];
    const float* Wv = (const float*)d_in[3];
    float* out = (float*)d_out;

    __half *x2[2], *Wq2[2], *Wk2[2], *Wv2[2], *Q2[2], *K2[2], *Vt2[2];
    __half *Ph;
    float *V, *P, *rinv, *rowmax;
    for (int i = 0; i < 2; i++) {
        cudaGetSymbolAddress((void**)&x2[i],  g_x2);  x2[i]  += (size_t)i * SEQ * DIM;
        cudaGetSymbolAddress((void**)&Wq2[i], g_Wq2); Wq2[i] += (size_t)i * DIM * DIM;
        cudaGetSymbolAddress((void**)&Wk2[i], g_Wk2); Wk2[i] += (size_t)i * DIM * DIM;
        cudaGetSymbolAddress((void**)&Wv2[i], g_Wv2); Wv2[i] += (size_t)i * DIM * DIM;
        cudaGetSymbolAddress((void**)&Q2[i],  g_Q2);  Q2[i]  += (size_t)i * SEQ * DIM;
        cudaGetSymbolAddress((void**)&K2[i],  g_K2);  K2[i]  += (size_t)i * SEQ * DIM;
        cudaGetSymbolAddress((void**)&Vt2[i], g_Vt2); Vt2[i] += (size_t)i * DIM * SEQ;
    }
    cudaGetSymbolAddress((void**)&Ph,     g_Ph);
    cudaGetSymbolAddress((void**)&V,      g_V);
    cudaGetSymbolAddress((void**)&P,      g_P);
    cudaGetSymbolAddress((void**)&rinv,   g_rinv);
    cudaGetSymbolAddress((void**)&rowmax, g_rowmax);

    auto gemm_causal = hmma_gemm<2, 2, 3, 3, false, true,  false>;  // QK^T + rowmax
    auto gemm_pv     = hmma_gemm<1, 2, 2, 2, true,  false, true>;   // PV split-K

    const int SM4 = 2 * 4 * 10240 + 1024;   // 82944
    const int SM3 = 2 * 3 * 10240 + 1024;   // 62464
    cudaFuncSetAttribute(proj3_kernel, cudaFuncAttributeMaxDynamicSharedMemorySize, SM4);
    cudaFuncSetAttribute(gemm_causal,  cudaFuncAttributeMaxDynamicSharedMemorySize, SM4);
    cudaFuncSetAttribute(gemm_pv,      cudaFuncAttributeMaxDynamicSharedMemorySize, SM3);

    // 1) operand splits (also resets rowmax to -inf)
    split2_kernel<<<1024, 256>>>(x, (size_t)SEQ * DIM, x2[0], x2[1], rowmax);
    dim3 tb(32, 8);
    tsplitW_kernel<<<dim3(DIM / 32, DIM / 32, 3), tb>>>(Wq, Wk, Wv,
                                                        Wq2[0], Wq2[1], Wk2[0], Wk2[1],
                                                        Wv2[0], Wv2[1]);

    // 2) all three projections in ONE launch (768 CTAs)
    proj3_kernel<<<dim3(DIM / 128, SEQ / 128, 3), 256, SM4>>>(
        x2[0], x2[1], Wq2[0], Wq2[1], Wk2[0], Wk2[1], Wv2[0], Wv2[1],
        Q2[0], Q2[1], K2[0], K2[1], V);

    // 3) V -> Vt (split2, transposed)
    tsplitV_kernel<<<dim3(DIM / 32, SEQ / 32), tb>>>(V, Vt2[0], Vt2[1]);

    // 4) scaled logits + row maxes (compact lower-triangular grid, 528 CTAs)
    gemm_causal<<<dim3(32 * 33 / 2), 256, SM4>>>(Q2[0], Q2[1], K2[0], K2[1],
                                                 DIM, DIM, DIM, P, nullptr, nullptr,
                                                 SEQ, nullptr, rowmax);

    // 5) single-pass softmax -> fp16 probs + rinv of rounded sum
    softmax_h<<<SEQ, 256>>>(P, rowmax, Ph, rinv);

    // 6) out = (Ph @ V) * rinv, split-K over 2 CTAs per tile (RED combine)
    cudaMemsetAsync(out, 0, (size_t)SEQ * DIM * sizeof(float));
    gemm_pv<<<dim3(DIM / 128, SEQ / 128, 2), 256, SM3>>>(Ph, nullptr, Vt2[0], Vt2[1],
                                                         SEQ, SEQ, SEQ, out, nullptr, nullptr,
                                                         DIM, rinv, nullptr);
}

// round 16
// speedup vs baseline: 1.1358x; 1.0329x over previous
#include <cuda_runtime.h>
#include <cuda_fp16.h>
#include <cstdint>

// ---------------------------------------------------------------------------
// SelfAttention via mma.sync (HMMA) fp16-emulated-fp32 GEMMs.
// fp32 operand = hi + lo fp16 planes; 3 pair-products (hh,hl,lh) ~2^-22.
// V proj: x_hi @ (Wv_hi + Wv_lo), 2 pairs. PV: fp16 P (rounded-sum norm), 2 pairs.
// R16: 3-pair GEMMs (proj3, QK^T) use 64x64 warp tiles in 128-thread CTAs
// (6:1 MMA:LDSM) while KEEPING occupancy 2 (R12 retried without the occ-1 confound).
// ---------------------------------------------------------------------------

constexpr int SEQ = 4096;
constexpr int DIM = 1024;

__device__ __half g_x2[2][(size_t)SEQ * DIM];
__device__ __half g_Wq2[2][(size_t)DIM * DIM];   // transposed [out][in]
__device__ __half g_Wk2[2][(size_t)DIM * DIM];
__device__ __half g_Wv2[2][(size_t)DIM * DIM];
__device__ __half g_Q2[2][(size_t)SEQ * DIM];
__device__ __half g_K2[2][(size_t)SEQ * DIM];
__device__ float  g_V[(size_t)SEQ * DIM];
__device__ __half g_Vt2[2][(size_t)DIM * SEQ];   // [dim][seq]
__device__ float  g_P[(size_t)SEQ * SEQ];        // scaled logits
__device__ __half g_Ph[(size_t)SEQ * SEQ];       // fp16 unnormalized probs
__device__ float  g_rinv[SEQ];
__device__ float  g_rowmax[SEQ];

// ---------------- helpers ---------------------------------------------------
__device__ __forceinline__ uint32_t smem_u32(const void* p) {
    uint32_t a;
    asm("{ .reg .u64 t; cvta.to.shared.u64 t, %1; cvt.u32.u64 %0, t; }"
        : "=r"(a) : "l"(p));
    return a;
}
__device__ __forceinline__ void cp16(uint32_t s, const void* g) {
    asm volatile("cp.async.cg.shared.global [%0], [%1], 16;" :: "r"(s), "l"(g));
}
#define CP_COMMIT() asm volatile("cp.async.commit_group;" ::: "memory")
#define CP_WAIT1()  asm volatile("cp.async.wait_group 1;" ::: "memory")
#define CP_WAIT0()  asm volatile("cp.async.wait_group 0;" ::: "memory")

__device__ __forceinline__ void ldsm4(uint32_t* r, uint32_t addr) {
    asm volatile("ldmatrix.sync.aligned.m8n8.x4.shared.b16 {%0,%1,%2,%3}, [%4];"
                 : "=r"(r[0]), "=r"(r[1]), "=r"(r[2]), "=r"(r[3]) : "r"(addr));
}
__device__ __forceinline__ void mma16816(float* d, const uint32_t* a, const uint32_t* b) {
    asm volatile(
        "mma.sync.aligned.m16n8k16.row.col.f32.f16.f16.f32 "
        "{%0,%1,%2,%3}, {%4,%5,%6,%7}, {%8,%9}, {%0,%1,%2,%3};"
        : "+f"(d[0]), "+f"(d[1]), "+f"(d[2]), "+f"(d[3])
        : "r"(a[0]), "r"(a[1]), "r"(a[2]), "r"(a[3]), "r"(b[0]), "r"(b[1]));
}

__device__ __forceinline__ void split2h(float v, __half& a, __half& b) {
    a = __float2half_rn(v);
    b = __float2half_rn(v - __half2float(a));
}
// order-independent float atomic max (monotone int/uint encoding)
__device__ __forceinline__ void atomicMaxF(float* a, float v) {
    if (v >= 0.0f) atomicMax((int*)a, __float_as_int(v));
    else           atomicMin((unsigned int*)a, (unsigned int)__float_as_int(v));
}

constexpr uint32_t RSTR = 80;              // 32 fp16 rows padded to 80B (conflict-free)
constexpr uint32_t PLSZ = 128 * RSTR;      // 10240

// ========== R11 generic kernel — PV (SPLITK) ================================
template <int NA, int NB, int NPAIR, int EPI, bool KLIMF, bool COMPACT, bool SPLITK>
__global__ __launch_bounds__(256, 2)
void hmma_gemm(const __half* __restrict__ A0, const __half* __restrict__ A1,
               const __half* __restrict__ B0, const __half* __restrict__ B1,
               int lda, int ldb, int K,
               float* __restrict__ Cf,
               __half* __restrict__ O0, __half* __restrict__ O1,
               int ldc, const float* __restrict__ rinv)
{
    int bn, bm;
    if (COMPACT) {
        int t = blockIdx.x;
        bm = (int)((sqrtf(8.0f * t + 1.0f) - 1.0f) * 0.5f);
        while ((bm + 1) * (bm + 2) / 2 <= t) bm++;
        while (bm * (bm + 1) / 2 > t) bm--;
        bn = t - bm * (bm + 1) / 2;
    } else {
        bn = blockIdx.x; bm = blockIdx.y;
    }
    const int m0 = bm * 128, n0 = bn * 128;

    constexpr int NPL = NA + NB;
    constexpr uint32_t STAGE = NPL * PLSZ;

    extern __shared__ char smem_dyn[];
    const uint32_t sbase = (smem_u32(smem_dyn) + 1023u) & ~1023u;

    const int tid  = threadIdx.x;
    const int lane = tid & 31;
    const int wid  = tid >> 5;
    const int wm   = (wid >> 2) * 64;
    const int wn   = (wid & 3) * 32;

    const __half* pl[NPL];
    pl[0] = A0; if (NA > 1) pl[1] = A1;
    pl[NA] = B0; if (NB > 1) pl[NA + 1] = B1;

    int Kend = K;
    if (KLIMF) { int kl = (bm + 1) * 128; Kend = kl < K ? kl : K; }
    const int nch = Kend >> 5;

    int c0 = 0, c1 = nch;
    if (SPLITK) {
        const int half = nch >> 1;
        c0 = blockIdx.z * half;
        c1 = c0 + half;
    }

    auto load_stage = [&](int c, int buf) {
        const int k0 = c << 5;
        const uint32_t sb = sbase + buf * STAGE;
#pragma unroll
        for (int t = 0; t < NPL * 2; t++) {
            int idx = tid + t * 256;
            int plane = idx >> 9;
            int rem = idx & 511;
            int row = rem >> 2;
            int c4 = rem & 3;
            int rbase = (plane < NA) ? m0 : n0;
            int ld    = (plane < NA) ? lda : ldb;
            const __half* g = pl[plane] + (size_t)(rbase + row) * ld + k0 + c4 * 8;
            cp16(sb + plane * PLSZ + row * RSTR + c4 * 16, g);
        }
        CP_COMMIT();
    };

    float acc[4][4][4];
#pragma unroll
    for (int i = 0; i < 4; i++)
#pragma unroll
        for (int j = 0; j < 4; j++)
#pragma unroll
            for (int q = 0; q < 4; q++) acc[i][j][q] = 0.0f;

    constexpr int paA[3] = {0, 0, 1};
    constexpr int paB[3] = {0, 1, 0};

    load_stage(c0, 0);
    if (c0 + 1 < c1) load_stage(c0 + 1, 1);

    for (int c = c0; c < c1; c++) {
        if (c + 1 < c1) { CP_WAIT1(); } else { CP_WAIT0(); }
        __syncthreads();

        const uint32_t sb = sbase + ((c - c0) & 1) * STAGE;
        const uint32_t a_row = (uint32_t)(wm + (lane & 15));
        const uint32_t a_kb  = ((uint32_t)(lane >> 4)) << 4;
        const uint32_t b_row = (uint32_t)(wn + ((lane >> 1) & 8) + (lane & 7));
        const uint32_t b_kb  = ((uint32_t)((lane >> 3) & 1)) << 4;

#pragma unroll
        for (int k16 = 0; k16 < 2; k16++) {
            uint32_t bfr[NB][8];
#pragma unroll
            for (int p = 0; p < NB; p++) {
                const uint32_t pbn = sb + (NA + p) * PLSZ + k16 * 32 + b_kb;
#pragma unroll
                for (int nt2 = 0; nt2 < 2; nt2++)
                    ldsm4(&bfr[p][nt2 * 4], pbn + (b_row + nt2 * 16) * RSTR);
            }
#pragma unroll
            for (int ia = 0; ia < NA; ia++) {
                uint32_t af[4][4];
                const uint32_t pbm = sb + ia * PLSZ + k16 * 32 + a_kb;
#pragma unroll
                for (int mt = 0; mt < 4; mt++)
                    ldsm4(af[mt], pbm + (a_row + mt * 16) * RSTR);
#pragma unroll
                for (int p = 0; p < NPAIR; p++) {
                    if (paA[p] != ia) continue;
                    const int ib = paB[p];
#pragma unroll
                    for (int mt = 0; mt < 4; mt++)
#pragma unroll
                        for (int nt = 0; nt < 4; nt++)
                            mma16816(acc[mt][nt], af[mt], &bfr[ib][nt * 2]);
                }
            }
        }
        __syncthreads();
        if (c + 2 < c1) load_stage(c + 2, (c - c0) & 1);
    }

#pragma unroll
    for (int mt = 0; mt < 4; mt++) {
#pragma unroll
        for (int nt = 0; nt < 4; nt++) {
            const int gm = m0 + wm + mt * 16 + (lane >> 2);
            const int gn = n0 + wn + nt * 8 + (lane & 3) * 2;
            float c0v = acc[mt][nt][0], c1v = acc[mt][nt][1];
            float c2v = acc[mt][nt][2], c3v = acc[mt][nt][3];
            if (EPI == 0) {
                *reinterpret_cast<float2*>(&Cf[(size_t)gm * ldc + gn]) = make_float2(c0v, c1v);
                *reinterpret_cast<float2*>(&Cf[(size_t)(gm + 8) * ldc + gn]) = make_float2(c2v, c3v);
            } else if (EPI == 2) {
                float s0 = rinv[gm], s1 = rinv[gm + 8];
                if (SPLITK) {
                    atomicAdd(&Cf[(size_t)gm * ldc + gn],       c0v * s0);
                    atomicAdd(&Cf[(size_t)gm * ldc + gn + 1],   c1v * s0);
                    atomicAdd(&Cf[(size_t)(gm + 8) * ldc + gn],     c2v * s1);
                    atomicAdd(&Cf[(size_t)(gm + 8) * ldc + gn + 1], c3v * s1);
                } else {
                    *reinterpret_cast<float2*>(&Cf[(size_t)gm * ldc + gn]) =
                        make_float2(c0v * s0, c1v * s0);
                    *reinterpret_cast<float2*>(&Cf[(size_t)(gm + 8) * ldc + gn]) =
                        make_float2(c2v * s1, c3v * s1);
                }
            } else {
                __half a0, b0, a1, b1;
                __half2 t;
                split2h(c0v, a0, b0); split2h(c1v, a1, b1);
                t.x = a0; t.y = a1;
                *reinterpret_cast<__half2*>(&O0[(size_t)gm * ldc + gn]) = t;
                t.x = b0; t.y = b1;
                *reinterpret_cast<__half2*>(&O1[(size_t)gm * ldc + gn]) = t;
                split2h(c2v, a0, b0); split2h(c3v, a1, b1);
                t.x = a0; t.y = a1;
                *reinterpret_cast<__half2*>(&O0[(size_t)(gm + 8) * ldc + gn]) = t;
                t.x = b0; t.y = b1;
                *reinterpret_cast<__half2*>(&O1[(size_t)(gm + 8) * ldc + gn]) = t;
            }
        }
    }
}

// ========== R16: 64x64 warp tile, 128-thread CTA, occ 2 ======================
// MODE 0: merged Q/K/V proj (blockIdx.z = 0/1/2)
// MODE 1: QK^T with scaled logits + atomic rowmax (compact triangular grid)
template <int MODE>
__global__ __launch_bounds__(128, 2)
void hmma_w64(const __half* __restrict__ A0, const __half* __restrict__ A1,
              const __half* __restrict__ Bq0, const __half* __restrict__ Bq1,
              const __half* __restrict__ Bk0, const __half* __restrict__ Bk1,
              const __half* __restrict__ Bv0, const __half* __restrict__ Bv1,
              int lda, int ldb, int K,
              float* __restrict__ Cf,
              __half* __restrict__ Q0, __half* __restrict__ Q1,
              __half* __restrict__ K0o, __half* __restrict__ K1o,
              int ldc, float* __restrict__ rowmax)
{
    int bn, bm, z = 0;
    if (MODE == 1) {
        int t = blockIdx.x;
        bm = (int)((sqrtf(8.0f * t + 1.0f) - 1.0f) * 0.5f);
        while ((bm + 1) * (bm + 2) / 2 <= t) bm++;
        while (bm * (bm + 1) / 2 > t) bm--;
        bn = t - bm * (bm + 1) / 2;
    } else {
        bn = blockIdx.x; bm = blockIdx.y; z = blockIdx.z;
    }
    const int m0 = bm * 128, n0 = bn * 128;
    const bool diag = (MODE == 1) && (bm == bn);

    const __half* B0 = (MODE == 1) ? Bq0 : (z == 0) ? Bq0 : (z == 1) ? Bk0 : Bv0;
    const __half* B1 = (MODE == 1) ? Bq1 : (z == 0) ? Bq1 : (z == 1) ? Bk1 : Bv1;
    __half* O0 = (z == 0) ? Q0 : K0o;
    __half* O1 = (z == 0) ? Q1 : K1o;

    constexpr uint32_t STAGE = 4 * PLSZ;

    extern __shared__ char smem_dyn[];
    const uint32_t sbase = (smem_u32(smem_dyn) + 1023u) & ~1023u;

    const int tid  = threadIdx.x;
    const int lane = tid & 31;
    const int wid  = tid >> 5;          // 0..3
    const int wm   = (wid >> 1) * 64;   // 2 warps tall
    const int wn   = (wid & 1) * 64;    // 2 warps wide

    const __half* pl[4] = {A0, A1, B0, B1};
    const int nch = K >> 5;

    auto load_stage = [&](int c, int buf) {
        const int k0 = c << 5;
        const uint32_t sb = sbase + buf * STAGE;
#pragma unroll
        for (int t = 0; t < 16; t++) {           // 4 planes * 512 chunks / 128 thr
            int idx = tid + t * 128;
            int plane = idx >> 9;
            int rem = idx & 511;
            int row = rem >> 2;
            int c4 = rem & 3;
            int rbase = (plane < 2) ? m0 : n0;
            int ld    = (plane < 2) ? lda : ldb;
            const __half* g = pl[plane] + (size_t)(rbase + row) * ld + k0 + c4 * 8;
            cp16(sb + plane * PLSZ + row * RSTR + c4 * 16, g);
        }
        CP_COMMIT();
    };

    float acc[4][8][4];
#pragma unroll
    for (int i = 0; i < 4; i++)
#pragma unroll
        for (int j = 0; j < 8; j++)
#pragma unroll
            for (int q = 0; q < 4; q++) acc[i][j][q] = 0.0f;

    load_stage(0, 0);
    if (nch > 1) load_stage(1, 1);

    for (int c = 0; c < nch; c++) {
        if (c + 1 < nch) { CP_WAIT1(); } else { CP_WAIT0(); }
        __syncthreads();

        const uint32_t sb = sbase + (c & 1) * STAGE;
        const uint32_t a_row = (uint32_t)(wm + (lane & 15));
        const uint32_t a_kb  = ((uint32_t)(lane >> 4)) << 4;
        const uint32_t b_row = (uint32_t)(wn + ((lane >> 1) & 8) + (lane & 7));
        const uint32_t b_kb  = ((uint32_t)((lane >> 3) & 1)) << 4;

#pragma unroll
        for (int k16 = 0; k16 < 2; k16++) {
            uint32_t bfr[2][16];                 // 2 B planes x 64 cols
#pragma unroll
            for (int p = 0; p < 2; p++) {
                const uint32_t pbn = sb + (2 + p) * PLSZ + k16 * 32 + b_kb;
#pragma unroll
                for (int nt2 = 0; nt2 < 4; nt2++)
                    ldsm4(&bfr[p][nt2 * 4], pbn + (b_row + nt2 * 16) * RSTR);
            }
            // A plane 0: pairs (0,B0),(0,B1) — always
            {
                uint32_t af[4][4];
                const uint32_t pbm = sb + k16 * 32 + a_kb;
#pragma unroll
                for (int mt = 0; mt < 4; mt++)
                    ldsm4(af[mt], pbm + (a_row + mt * 16) * RSTR);
#pragma unroll
                for (int ib = 0; ib < 2; ib++)
#pragma unroll
                    for (int mt = 0; mt < 4; mt++)
#pragma unroll
                        for (int nt = 0; nt < 8; nt++)
                            mma16816(acc[mt][nt], af[mt], &bfr[ib][nt * 2]);
            }
            // A plane 1: pair (1,B0) — 3-pair paths only (uniform branch)
            if (MODE == 1 || z < 2) {
                uint32_t af[4][4];
                const uint32_t pbm = sb + PLSZ + k16 * 32 + a_kb;
#pragma unroll
                for (int mt = 0; mt < 4; mt++)
                    ldsm4(af[mt], pbm + (a_row + mt * 16) * RSTR);
#pragma unroll
                for (int mt = 0; mt < 4; mt++)
#pragma unroll
                    for (int nt = 0; nt < 8; nt++)
                        mma16816(acc[mt][nt], af[mt], &bfr[0][nt * 2]);
            }
        }
        __syncthreads();
        if (c + 2 < nch) load_stage(c + 2, c & 1);
    }

    // ---------------- epilogue ----------------------------------------------
    const float lscale = 0.03125f;   // 1/sqrt(1024)
#pragma unroll
    for (int mt = 0; mt < 4; mt++) {
        const int gm = m0 + wm + mt * 16 + (lane >> 2);
        float m0r = -3.402823466e38f, m1r = -3.402823466e38f;
#pragma unroll
        for (int nt = 0; nt < 8; nt++) {
            const int gn = n0 + wn + nt * 8 + (lane & 3) * 2;
            float c0 = acc[mt][nt][0], c1 = acc[mt][nt][1];
            float c2 = acc[mt][nt][2], c3 = acc[mt][nt][3];
            if (MODE == 1) {
                c0 *= lscale; c1 *= lscale; c2 *= lscale; c3 *= lscale;
                *reinterpret_cast<float2*>(&Cf[(size_t)gm * ldc + gn]) = make_float2(c0, c1);
                *reinterpret_cast<float2*>(&Cf[(size_t)(gm + 8) * ldc + gn]) = make_float2(c2, c3);
                if (!diag || gn     <= gm)     m0r = fmaxf(m0r, c0);
                if (!diag || gn + 1 <= gm)     m0r = fmaxf(m0r, c1);
                if (!diag || gn     <= gm + 8) m1r = fmaxf(m1r, c2);
                if (!diag || gn + 1 <= gm + 8) m1r = fmaxf(m1r, c3);
            } else if (z == 2) {
                *reinterpret_cast<float2*>(&Cf[(size_t)gm * ldc + gn]) = make_float2(c0, c1);
                *reinterpret_cast<float2*>(&Cf[(size_t)(gm + 8) * ldc + gn]) = make_float2(c2, c3);
            } else {
                __half a0, b0, a1, b1;
                __half2 t;
                split2h(c0, a0, b0); split2h(c1, a1, b1);
                t.x = a0; t.y = a1;
                *reinterpret_cast<__half2*>(&O0[(size_t)gm * ldc + gn]) = t;
                t.x = b0; t.y = b1;
                *reinterpret_cast<__half2*>(&O1[(size_t)gm * ldc + gn]) = t;
                split2h(c2, a0, b0); split2h(c3, a1, b1);
                t.x = a0; t.y = a1;
                *reinterpret_cast<__half2*>(&O0[(size_t)(gm + 8) * ldc + gn]) = t;
                t.x = b0; t.y = b1;
                *reinterpret_cast<__half2*>(&O1[(size_t)(gm + 8) * ldc + gn]) = t;
            }
        }
        if (MODE == 1) {
            m0r = fmaxf(m0r, __shfl_xor_sync(0xffffffffu, m0r, 1));
            m0r = fmaxf(m0r, __shfl_xor_sync(0xffffffffu, m0r, 2));
            m1r = fmaxf(m1r, __shfl_xor_sync(0xffffffffu, m1r, 1));
            m1r = fmaxf(m1r, __shfl_xor_sync(0xffffffffu, m1r, 2));
            if ((lane & 3) == 0) {
                atomicMaxF(&rowmax[gm], m0r);
                atomicMaxF(&rowmax[gm + 8], m1r);
            }
        }
    }
}

// ---------------- prep kernels ----------------------------------------------
__global__ void split2_kernel(const float* __restrict__ in, size_t n,
                              __half* __restrict__ o0, __half* __restrict__ o1,
                              float* __restrict__ rowmax)
{
    size_t i = (size_t)blockIdx.x * blockDim.x + threadIdx.x;
    if (i < SEQ) rowmax[i] = __int_as_float(0xFF800000);   // -inf, per-launch reset
    size_t stride = (size_t)gridDim.x * blockDim.x;
    for (; i < n; i += stride) {
        __half a, b;
        split2h(in[i], a, b);
        o0[i] = a; o1[i] = b;
    }
}

__global__ void tsplitW_kernel(const float* __restrict__ Wq, const float* __restrict__ Wk,
                               const float* __restrict__ Wv,
                               __half* __restrict__ q0, __half* __restrict__ q1,
                               __half* __restrict__ k0, __half* __restrict__ k1,
                               __half* __restrict__ v0, __half* __restrict__ v1)
{
    const float* in = (blockIdx.z == 0) ? Wq : (blockIdx.z == 1) ? Wk : Wv;
    __half* o0 = (blockIdx.z == 0) ? q0 : (blockIdx.z == 1) ? k0 : v0;
    __half* o1 = (blockIdx.z == 0) ? q1 : (blockIdx.z == 1) ? k1 : v1;
    __shared__ float t[32][33];
    const int bc = blockIdx.x * 32, br = blockIdx.y * 32;
    const int tx = threadIdx.x, ty = threadIdx.y;
#pragma unroll
    for (int i = 0; i < 4; i++)
        t[ty + i * 8][tx] = in[(size_t)(br + ty + i * 8) * DIM + bc + tx];
    __syncthreads();
#pragma unroll
    for (int i = 0; i < 4; i++) {
        float v = t[tx][ty + i * 8];
        size_t o = (size_t)(bc + ty + i * 8) * DIM + br + tx;
        __half a, b;
        split2h(v, a, b);
        o0[o] = a; o1[o] = b;
    }
}

__global__ void tsplitV_kernel(const float* __restrict__ in,
                               __half* __restrict__ o0, __half* __restrict__ o1)
{
    __shared__ float t[32][33];
    const int bc = blockIdx.x * 32, br = blockIdx.y * 32;
    const int tx = threadIdx.x, ty = threadIdx.y;
#pragma unroll
    for (int i = 0; i < 4; i++)
        t[ty + i * 8][tx] = in[(size_t)(br + ty + i * 8) * DIM + bc + tx];
    __syncthreads();
#pragma unroll
    for (int i = 0; i < 4; i++) {
        float v = t[tx][ty + i * 8];
        size_t o = (size_t)(bc + ty + i * 8) * SEQ + br + tx;
        __half a, b;
        split2h(v, a, b);
        o0[o] = a; o1[o] = b;
    }
}

__global__ __launch_bounds__(256)
void softmax_h(const float* __restrict__ P, const float* __restrict__ rowmax,
               __half* __restrict__ Ph, float* __restrict__ rinv)
{
    const int row   = blockIdx.x;
    const int valid = row + 1;
    const int klim  = ((row >> 7) + 1) << 7;
    const float* prow = P + (size_t)row * SEQ;
    const int tid = threadIdx.x;
    __shared__ float red[256];

    const float m = rowmax[row];
    float sum = 0.0f;
    for (int j = tid; j < klim; j += 256) {
        float e = 0.0f;
        if (j < valid) e = __expf(prow[j] - m);
        __half h = __float2half_rn(e);
        Ph[(size_t)row * SEQ + j] = h;
        sum += __half2float(h);
    }
    red[tid] = sum;
    __syncthreads();
#pragma unroll
    for (int s = 128; s > 0; s >>= 1) {
        if (tid < s) red[tid] += red[tid + s];
        __syncthreads();
    }
    if (tid == 0) rinv[row] = 1.0f / red[0];
}

// ---------------- host side --------------------------------------------------
extern "C" void kernel_launch(void* const* d_in, const int* in_sizes, int n_in,
                              void* d_out, int out_size)
{
    const float* x  = (const float*)d_in[0];
    const float* Wq = (const float*)d_in[1];
    const float* Wk = (const float*)d_in[2];
    const float* Wv = (const float*)d_in[3];
    float* out = (float*)d_out;

    __half *x2[2], *Wq2[2], *Wk2[2], *Wv2[2], *Q2[2], *K2[2], *Vt2[2];
    __half *Ph;
    float *V, *P, *rinv, *rowmax;
    for (int i = 0; i < 2; i++) {
        cudaGetSymbolAddress((void**)&x2[i],  g_x2);  x2[i]  += (size_t)i * SEQ * DIM;
        cudaGetSymbolAddress((void**)&Wq2[i], g_Wq2); Wq2[i] += (size_t)i * DIM * DIM;
        cudaGetSymbolAddress((void**)&Wk2[i], g_Wk2); Wk2[i] += (size_t)i * DIM * DIM;
        cudaGetSymbolAddress((void**)&Wv2[i], g_Wv2); Wv2[i] += (size_t)i * DIM * DIM;
        cudaGetSymbolAddress((void**)&Q2[i],  g_Q2);  Q2[i]  += (size_t)i * SEQ * DIM;
        cudaGetSymbolAddress((void**)&K2[i],  g_K2);  K2[i]  += (size_t)i * SEQ * DIM;
        cudaGetSymbolAddress((void**)&Vt2[i], g_Vt2); Vt2[i] += (size_t)i * DIM * SEQ;
    }
    cudaGetSymbolAddress((void**)&Ph,     g_Ph);
    cudaGetSymbolAddress((void**)&V,      g_V);
    cudaGetSymbolAddress((void**)&P,      g_P);
    cudaGetSymbolAddress((void**)&rinv,   g_rinv);
    cudaGetSymbolAddress((void**)&rowmax, g_rowmax);

    auto proj_w64   = hmma_w64<0>;                                  // merged QKV proj
    auto causal_w64 = hmma_w64<1>;                                  // QK^T + rowmax
    auto gemm_pv    = hmma_gemm<1, 2, 2, 2, true, false, true>;     // PV split-K

    const int SMW = 2 * 4 * 10240 + 1024;   // 82944 (w64 kernels, 4 planes x2)
    const int SM3 = 2 * 3 * 10240 + 1024;   // 62464
    cudaFuncSetAttribute(proj_w64,   cudaFuncAttributeMaxDynamicSharedMemorySize, SMW);
    cudaFuncSetAttribute(causal_w64, cudaFuncAttributeMaxDynamicSharedMemorySize, SMW);
    cudaFuncSetAttribute(gemm_pv,    cudaFuncAttributeMaxDynamicSharedMemorySize, SM3);

    // 1) operand splits (also resets rowmax to -inf)
    split2_kernel<<<1024, 256>>>(x, (size_t)SEQ * DIM, x2[0], x2[1], rowmax);
    dim3 tb(32, 8);
    tsplitW_kernel<<<dim3(DIM / 32, DIM / 32, 3), tb>>>(Wq, Wk, Wv,
                                                        Wq2[0], Wq2[1], Wk2[0], Wk2[1],
                                                        Wv2[0], Wv2[1]);

    // 2) all three projections in ONE launch (768 CTAs of 128 threads)
    proj_w64<<<dim3(DIM / 128, SEQ / 128, 3), 128, SMW>>>(
        x2[0], x2[1], Wq2[0], Wq2[1], Wk2[0], Wk2[1], Wv2[0], Wv2[1],
        DIM, DIM, DIM, V, Q2[0], Q2[1], K2[0], K2[1], DIM, nullptr);

    // 3) V -> Vt (split2, transposed)
    tsplitV_kernel<<<dim3(DIM / 32, SEQ / 32), tb>>>(V, Vt2[0], Vt2[1]);

    // 4) scaled logits + row maxes (compact triangular grid, 528 CTAs)
    causal_w64<<<dim3(32 * 33 / 2), 128, SMW>>>(
        Q2[0], Q2[1], K2[0], K2[1], nullptr, nullptr, nullptr, nullptr,
        DIM, DIM, DIM, P, nullptr, nullptr, nullptr, nullptr, SEQ, rowmax);

    // 5) single-pass softmax -> fp16 probs + rinv of rounded sum
    softmax_h<<<SEQ, 256>>>(P, rowmax, Ph, rinv);

    // 6) out = (Ph @ V) * rinv, split-K over 2 CTAs per tile (RED combine)
    cudaMemsetAsync(out, 0, (size_t)SEQ * DIM * sizeof(float));
    gemm_pv<<<dim3(DIM / 128, SEQ / 128, 2), 256, SM3>>>(Ph, nullptr, Vt2[0], Vt2[1],
                                                         SEQ, SEQ, SEQ, out, nullptr, nullptr,
                                                         DIM, rinv);
}

// round 17
// speedup vs baseline: 1.1422x; 1.0056x over previous
#include <cuda_runtime.h>
#include <cuda_fp16.h>
#include <cstdint>

// ---------------------------------------------------------------------------
// SelfAttention via mma.sync (HMMA) fp16-emulated-fp32 GEMMs.
// fp32 operand = hi + lo fp16 planes; 3 pair-products (hh,hl,lh) ~2^-22.
// V proj: x_hi @ (Wv_hi + Wv_lo), 2 pairs. PV: fp16 P (rounded-sum norm), 2 pairs.
// R16: proj/QK^T on 64x64 warp tiles (6:1 MMA:LDSM) at occ 2.
// R17: PV converted to the same w64 shape (5.3:1), split-K + RED kept.
// ---------------------------------------------------------------------------

constexpr int SEQ = 4096;
constexpr int DIM = 1024;

__device__ __half g_x2[2][(size_t)SEQ * DIM];
__device__ __half g_Wq2[2][(size_t)DIM * DIM];   // transposed [out][in]
__device__ __half g_Wk2[2][(size_t)DIM * DIM];
__device__ __half g_Wv2[2][(size_t)DIM * DIM];
__device__ __half g_Q2[2][(size_t)SEQ * DIM];
__device__ __half g_K2[2][(size_t)SEQ * DIM];
__device__ float  g_V[(size_t)SEQ * DIM];
__device__ __half g_Vt2[2][(size_t)DIM * SEQ];   // [dim][seq]
__device__ float  g_P[(size_t)SEQ * SEQ];        // scaled logits
__device__ __half g_Ph[(size_t)SEQ * SEQ];       // fp16 unnormalized probs
__device__ float  g_rinv[SEQ];
__device__ float  g_rowmax[SEQ];

// ---------------- helpers ---------------------------------------------------
__device__ __forceinline__ uint32_t smem_u32(const void* p) {
    uint32_t a;
    asm("{ .reg .u64 t; cvta.to.shared.u64 t, %1; cvt.u32.u64 %0, t; }"
        : "=r"(a) : "l"(p));
    return a;
}
__device__ __forceinline__ void cp16(uint32_t s, const void* g) {
    asm volatile("cp.async.cg.shared.global [%0], [%1], 16;" :: "r"(s), "l"(g));
}
#define CP_COMMIT() asm volatile("cp.async.commit_group;" ::: "memory")
#define CP_WAIT1()  asm volatile("cp.async.wait_group 1;" ::: "memory")
#define CP_WAIT0()  asm volatile("cp.async.wait_group 0;" ::: "memory")

__device__ __forceinline__ void ldsm4(uint32_t* r, uint32_t addr) {
    asm volatile("ldmatrix.sync.aligned.m8n8.x4.shared.b16 {%0,%1,%2,%3}, [%4];"
                 : "=r"(r[0]), "=r"(r[1]), "=r"(r[2]), "=r"(r[3]) : "r"(addr));
}
__device__ __forceinline__ void mma16816(float* d, const uint32_t* a, const uint32_t* b) {
    asm volatile(
        "mma.sync.aligned.m16n8k16.row.col.f32.f16.f16.f32 "
        "{%0,%1,%2,%3}, {%4,%5,%6,%7}, {%8,%9}, {%0,%1,%2,%3};"
        : "+f"(d[0]), "+f"(d[1]), "+f"(d[2]), "+f"(d[3])
        : "r"(a[0]), "r"(a[1]), "r"(a[2]), "r"(a[3]), "r"(b[0]), "r"(b[1]));
}

__device__ __forceinline__ void split2h(float v, __half& a, __half& b) {
    a = __float2half_rn(v);
    b = __float2half_rn(v - __half2float(a));
}
// order-independent float atomic max (monotone int/uint encoding)
__device__ __forceinline__ void atomicMaxF(float* a, float v) {
    if (v >= 0.0f) atomicMax((int*)a, __float_as_int(v));
    else           atomicMin((unsigned int*)a, (unsigned int)__float_as_int(v));
}

constexpr uint32_t RSTR = 80;              // 32 fp16 rows padded to 80B (conflict-free)
constexpr uint32_t PLSZ = 128 * RSTR;      // 10240

// ========== 64x64 warp tile, 128-thread CTA, occ 2: proj + QK^T ==============
// MODE 0: merged Q/K/V proj (blockIdx.z = 0/1/2)
// MODE 1: QK^T with scaled logits + atomic rowmax (compact triangular grid)
template <int MODE>
__global__ __launch_bounds__(128, 2)
void hmma_w64(const __half* __restrict__ A0, const __half* __restrict__ A1,
              const __half* __restrict__ Bq0, const __half* __restrict__ Bq1,
              const __half* __restrict__ Bk0, const __half* __restrict__ Bk1,
              const __half* __restrict__ Bv0, const __half* __restrict__ Bv1,
              int lda, int ldb, int K,
              float* __restrict__ Cf,
              __half* __restrict__ Q0, __half* __restrict__ Q1,
              __half* __restrict__ K0o, __half* __restrict__ K1o,
              int ldc, float* __restrict__ rowmax)
{
    int bn, bm, z = 0;
    if (MODE == 1) {
        int t = blockIdx.x;
        bm = (int)((sqrtf(8.0f * t + 1.0f) - 1.0f) * 0.5f);
        while ((bm + 1) * (bm + 2) / 2 <= t) bm++;
        while (bm * (bm + 1) / 2 > t) bm--;
        bn = t - bm * (bm + 1) / 2;
    } else {
        bn = blockIdx.x; bm = blockIdx.y; z = blockIdx.z;
    }
    const int m0 = bm * 128, n0 = bn * 128;
    const bool diag = (MODE == 1) && (bm == bn);

    const __half* B0 = (MODE == 1) ? Bq0 : (z == 0) ? Bq0 : (z == 1) ? Bk0 : Bv0;
    const __half* B1 = (MODE == 1) ? Bq1 : (z == 0) ? Bq1 : (z == 1) ? Bk1 : Bv1;
    __half* O0 = (z == 0) ? Q0 : K0o;
    __half* O1 = (z == 0) ? Q1 : K1o;

    constexpr uint32_t STAGE = 4 * PLSZ;

    extern __shared__ char smem_dyn[];
    const uint32_t sbase = (smem_u32(smem_dyn) + 1023u) & ~1023u;

    const int tid  = threadIdx.x;
    const int lane = tid & 31;
    const int wid  = tid >> 5;          // 0..3
    const int wm   = (wid >> 1) * 64;   // 2 warps tall
    const int wn   = (wid & 1) * 64;    // 2 warps wide

    const __half* pl[4] = {A0, A1, B0, B1};
    const int nch = K >> 5;

    auto load_stage = [&](int c, int buf) {
        const int k0 = c << 5;
        const uint32_t sb = sbase + buf * STAGE;
#pragma unroll
        for (int t = 0; t < 16; t++) {           // 4 planes * 512 chunks / 128 thr
            int idx = tid + t * 128;
            int plane = idx >> 9;
            int rem = idx & 511;
            int row = rem >> 2;
            int c4 = rem & 3;
            int rbase = (plane < 2) ? m0 : n0;
            int ld    = (plane < 2) ? lda : ldb;
            const __half* g = pl[plane] + (size_t)(rbase + row) * ld + k0 + c4 * 8;
            cp16(sb + plane * PLSZ + row * RSTR + c4 * 16, g);
        }
        CP_COMMIT();
    };

    float acc[4][8][4];
#pragma unroll
    for (int i = 0; i < 4; i++)
#pragma unroll
        for (int j = 0; j < 8; j++)
#pragma unroll
            for (int q = 0; q < 4; q++) acc[i][j][q] = 0.0f;

    load_stage(0, 0);
    if (nch > 1) load_stage(1, 1);

    for (int c = 0; c < nch; c++) {
        if (c + 1 < nch) { CP_WAIT1(); } else { CP_WAIT0(); }
        __syncthreads();

        const uint32_t sb = sbase + (c & 1) * STAGE;
        const uint32_t a_row = (uint32_t)(wm + (lane & 15));
        const uint32_t a_kb  = ((uint32_t)(lane >> 4)) << 4;
        const uint32_t b_row = (uint32_t)(wn + ((lane >> 1) & 8) + (lane & 7));
        const uint32_t b_kb  = ((uint32_t)((lane >> 3) & 1)) << 4;

#pragma unroll
        for (int k16 = 0; k16 < 2; k16++) {
            uint32_t bfr[2][16];                 // 2 B planes x 64 cols
#pragma unroll
            for (int p = 0; p < 2; p++) {
                const uint32_t pbn = sb + (2 + p) * PLSZ + k16 * 32 + b_kb;
#pragma unroll
                for (int nt2 = 0; nt2 < 4; nt2++)
                    ldsm4(&bfr[p][nt2 * 4], pbn + (b_row + nt2 * 16) * RSTR);
            }
            // A plane 0: pairs (0,B0),(0,B1) — always
            {
                uint32_t af[4][4];
                const uint32_t pbm = sb + k16 * 32 + a_kb;
#pragma unroll
                for (int mt = 0; mt < 4; mt++)
                    ldsm4(af[mt], pbm + (a_row + mt * 16) * RSTR);
#pragma unroll
                for (int ib = 0; ib < 2; ib++)
#pragma unroll
                    for (int mt = 0; mt < 4; mt++)
#pragma unroll
                        for (int nt = 0; nt < 8; nt++)
                            mma16816(acc[mt][nt], af[mt], &bfr[ib][nt * 2]);
            }
            // A plane 1: pair (1,B0) — 3-pair paths only (uniform branch)
            if (MODE == 1 || z < 2) {
                uint32_t af[4][4];
                const uint32_t pbm = sb + PLSZ + k16 * 32 + a_kb;
#pragma unroll
                for (int mt = 0; mt < 4; mt++)
                    ldsm4(af[mt], pbm + (a_row + mt * 16) * RSTR);
#pragma unroll
                for (int mt = 0; mt < 4; mt++)
#pragma unroll
                    for (int nt = 0; nt < 8; nt++)
                        mma16816(acc[mt][nt], af[mt], &bfr[0][nt * 2]);
            }
        }
        __syncthreads();
        if (c + 2 < nch) load_stage(c + 2, c & 1);
    }

    // ---------------- epilogue ----------------------------------------------
    const float lscale = 0.03125f;   // 1/sqrt(1024)
#pragma unroll
    for (int mt = 0; mt < 4; mt++) {
        const int gm = m0 + wm + mt * 16 + (lane >> 2);
        float m0r = -3.402823466e38f, m1r = -3.402823466e38f;
#pragma unroll
        for (int nt = 0; nt < 8; nt++) {
            const int gn = n0 + wn + nt * 8 + (lane & 3) * 2;
            float c0 = acc[mt][nt][0], c1 = acc[mt][nt][1];
            float c2 = acc[mt][nt][2], c3 = acc[mt][nt][3];
            if (MODE == 1) {
                c0 *= lscale; c1 *= lscale; c2 *= lscale; c3 *= lscale;
                *reinterpret_cast<float2*>(&Cf[(size_t)gm * ldc + gn]) = make_float2(c0, c1);
                *reinterpret_cast<float2*>(&Cf[(size_t)(gm + 8) * ldc + gn]) = make_float2(c2, c3);
                if (!diag || gn     <= gm)     m0r = fmaxf(m0r, c0);
                if (!diag || gn + 1 <= gm)     m0r = fmaxf(m0r, c1);
                if (!diag || gn     <= gm + 8) m1r = fmaxf(m1r, c2);
                if (!diag || gn + 1 <= gm + 8) m1r = fmaxf(m1r, c3);
            } else if (z == 2) {
                *reinterpret_cast<float2*>(&Cf[(size_t)gm * ldc + gn]) = make_float2(c0, c1);
                *reinterpret_cast<float2*>(&Cf[(size_t)(gm + 8) * ldc + gn]) = make_float2(c2, c3);
            } else {
                __half a0, b0, a1, b1;
                __half2 t;
                split2h(c0, a0, b0); split2h(c1, a1, b1);
                t.x = a0; t.y = a1;
                *reinterpret_cast<__half2*>(&O0[(size_t)gm * ldc + gn]) = t;
                t.x = b0; t.y = b1;
                *reinterpret_cast<__half2*>(&O1[(size_t)gm * ldc + gn]) = t;
                split2h(c2, a0, b0); split2h(c3, a1, b1);
                t.x = a0; t.y = a1;
                *reinterpret_cast<__half2*>(&O0[(size_t)(gm + 8) * ldc + gn]) = t;
                t.x = b0; t.y = b1;
                *reinterpret_cast<__half2*>(&O1[(size_t)(gm + 8) * ldc + gn]) = t;
            }
        }
        if (MODE == 1) {
            m0r = fmaxf(m0r, __shfl_xor_sync(0xffffffffu, m0r, 1));
            m0r = fmaxf(m0r, __shfl_xor_sync(0xffffffffu, m0r, 2));
            m1r = fmaxf(m1r, __shfl_xor_sync(0xffffffffu, m1r, 1));
            m1r = fmaxf(m1r, __shfl_xor_sync(0xffffffffu, m1r, 2));
            if ((lane & 3) == 0) {
                atomicMaxF(&rowmax[gm], m0r);
                atomicMaxF(&rowmax[gm + 8], m1r);
            }
        }
    }
}

// ========== R17: PV on the w64 shape (2 pairs, 3 planes, split-K) ============
// out[m][n] += rinv[m] * sum_k Ph[m][k] * (Vt_hi[n][k] + Vt_lo[n][k])
__global__ __launch_bounds__(128, 2)
void hmma_pv_w64(const __half* __restrict__ Pp, const __half* __restrict__ V0,
                 const __half* __restrict__ V1,
                 float* __restrict__ out, const float* __restrict__ rinv)
{
    const int bn = blockIdx.x, bm = blockIdx.y;
    const int m0 = bm * 128, n0 = bn * 128;

    const int nch = (bm + 1) * 4;        // causal K-limit in 32-chunks
    const int half = nch >> 1;           // integral: nch = 4*(bm+1)
    const int c0 = blockIdx.z * half;
    const int c1 = c0 + half;

    constexpr uint32_t STAGE = 3 * PLSZ; // Ph, Vhi, Vlo

    extern __shared__ char smem_dyn[];
    const uint32_t sbase = (smem_u32(smem_dyn) + 1023u) & ~1023u;

    const int tid  = threadIdx.x;
    const int lane = tid & 31;
    const int wid  = tid >> 5;
    const int wm   = (wid >> 1) * 64;
    const int wn   = (wid & 1) * 64;

    const __half* pl[3] = {Pp, V0, V1};

    auto load_stage = [&](int c, int buf) {
        const int k0 = c << 5;
        const uint32_t sb = sbase + buf * STAGE;
#pragma unroll
        for (int t = 0; t < 12; t++) {           // 3 planes * 512 chunks / 128 thr
            int idx = tid + t * 128;
            int plane = idx >> 9;
            int rem = idx & 511;
            int row = rem >> 2;
            int c4 = rem & 3;
            int rbase = (plane < 1) ? m0 : n0;
            const __half* g = pl[plane] + (size_t)(rbase + row) * SEQ + k0 + c4 * 8;
            cp16(sb + plane * PLSZ + row * RSTR + c4 * 16, g);
        }
        CP_COMMIT();
    };

    float acc[4][8][4];
#pragma unroll
    for (int i = 0; i < 4; i++)
#pragma unroll
        for (int j = 0; j < 8; j++)
#pragma unroll
            for (int q = 0; q < 4; q++) acc[i][j][q] = 0.0f;

    load_stage(c0, 0);
    if (c0 + 1 < c1) load_stage(c0 + 1, 1);

    for (int c = c0; c < c1; c++) {
        if (c + 1 < c1) { CP_WAIT1(); } else { CP_WAIT0(); }
        __syncthreads();

        const uint32_t sb = sbase + ((c - c0) & 1) * STAGE;
        const uint32_t a_row = (uint32_t)(wm + (lane & 15));
        const uint32_t a_kb  = ((uint32_t)(lane >> 4)) << 4;
        const uint32_t b_row = (uint32_t)(wn + ((lane >> 1) & 8) + (lane & 7));
        const uint32_t b_kb  = ((uint32_t)((lane >> 3) & 1)) << 4;

#pragma unroll
        for (int k16 = 0; k16 < 2; k16++) {
            uint32_t bfr[2][16];
#pragma unroll
            for (int p = 0; p < 2; p++) {
                const uint32_t pbn = sb + (1 + p) * PLSZ + k16 * 32 + b_kb;
#pragma unroll
                for (int nt2 = 0; nt2 < 4; nt2++)
                    ldsm4(&bfr[p][nt2 * 4], pbn + (b_row + nt2 * 16) * RSTR);
            }
            uint32_t af[4][4];
            const uint32_t pbm = sb + k16 * 32 + a_kb;
#pragma unroll
            for (int mt = 0; mt < 4; mt++)
                ldsm4(af[mt], pbm + (a_row + mt * 16) * RSTR);
#pragma unroll
            for (int ib = 0; ib < 2; ib++)
#pragma unroll
                for (int mt = 0; mt < 4; mt++)
#pragma unroll
                    for (int nt = 0; nt < 8; nt++)
                        mma16816(acc[mt][nt], af[mt], &bfr[ib][nt * 2]);
        }
        __syncthreads();
        if (c + 2 < c1) load_stage(c + 2, (c - c0) & 1);
    }

    // epilogue: scale by rinv, RED-combine the two split-K halves
#pragma unroll
    for (int mt = 0; mt < 4; mt++) {
        const int gm = m0 + wm + mt * 16 + (lane >> 2);
        const float s0 = rinv[gm], s1 = rinv[gm + 8];
#pragma unroll
        for (int nt = 0; nt < 8; nt++) {
            const int gn = n0 + wn + nt * 8 + (lane & 3) * 2;
            atomicAdd(&out[(size_t)gm * DIM + gn],       acc[mt][nt][0] * s0);
            atomicAdd(&out[(size_t)gm * DIM + gn + 1],   acc[mt][nt][1] * s0);
            atomicAdd(&out[(size_t)(gm + 8) * DIM + gn],     acc[mt][nt][2] * s1);
            atomicAdd(&out[(size_t)(gm + 8) * DIM + gn + 1], acc[mt][nt][3] * s1);
        }
    }
}

// ---------------- prep kernels ----------------------------------------------
__global__ void split2_kernel(const float* __restrict__ in, size_t n,
                              __half* __restrict__ o0, __half* __restrict__ o1,
                              float* __restrict__ rowmax)
{
    size_t i = (size_t)blockIdx.x * blockDim.x + threadIdx.x;
    if (i < SEQ) rowmax[i] = __int_as_float(0xFF800000);   // -inf, per-launch reset
    size_t stride = (size_t)gridDim.x * blockDim.x;
    for (; i < n; i += stride) {
        __half a, b;
        split2h(in[i], a, b);
        o0[i] = a; o1[i] = b;
    }
}

__global__ void tsplitW_kernel(const float* __restrict__ Wq, const float* __restrict__ Wk,
                               const float* __restrict__ Wv,
                               __half* __restrict__ q0, __half* __restrict__ q1,
                               __half* __restrict__ k0, __half* __restrict__ k1,
                               __half* __restrict__ v0, __half* __restrict__ v1)
{
    const float* in = (blockIdx.z == 0) ? Wq : (blockIdx.z == 1) ? Wk : Wv;
    __half* o0 = (blockIdx.z == 0) ? q0 : (blockIdx.z == 1) ? k0 : v0;
    __half* o1 = (blockIdx.z == 0) ? q1 : (blockIdx.z == 1) ? k1 : v1;
    __shared__ float t[32][33];
    const int bc = blockIdx.x * 32, br = blockIdx.y * 32;
    const int tx = threadIdx.x, ty = threadIdx.y;
#pragma unroll
    for (int i = 0; i < 4; i++)
        t[ty + i * 8][tx] = in[(size_t)(br + ty + i * 8) * DIM + bc + tx];
    __syncthreads();
#pragma unroll
    for (int i = 0; i < 4; i++) {
        float v = t[tx][ty + i * 8];
        size_t o = (size_t)(bc + ty + i * 8) * DIM + br + tx;
        __half a, b;
        split2h(v, a, b);
        o0[o] = a; o1[o] = b;
    }
}

__global__ void tsplitV_kernel(const float* __restrict__ in,
                               __half* __restrict__ o0, __half* __restrict__ o1)
{
    __shared__ float t[32][33];
    const int bc = blockIdx.x * 32, br = blockIdx.y * 32;
    const int tx = threadIdx.x, ty = threadIdx.y;
#pragma unroll
    for (int i = 0; i < 4; i++)
        t[ty + i * 8][tx] = in[(size_t)(br + ty + i * 8) * DIM + bc + tx];
    __syncthreads();
#pragma unroll
    for (int i = 0; i < 4; i++) {
        float v = t[tx][ty + i * 8];
        size_t o = (size_t)(bc + ty + i * 8) * SEQ + br + tx;
        __half a, b;
        split2h(v, a, b);
        o0[o] = a; o1[o] = b;
    }
}

__global__ __launch_bounds__(256)
void softmax_h(const float* __restrict__ P, const float* __restrict__ rowmax,
               __half* __restrict__ Ph, float* __restrict__ rinv)
{
    const int row   = blockIdx.x;
    const int valid = row + 1;
    const int klim  = ((row >> 7) + 1) << 7;
    const float* prow = P + (size_t)row * SEQ;
    const int tid = threadIdx.x;
    __shared__ float red[256];

    const float m = rowmax[row];
    float sum = 0.0f;
    for (int j = tid; j < klim; j += 256) {
        float e = 0.0f;
        if (j < valid) e = __expf(prow[j] - m);
        __half h = __float2half_rn(e);
        Ph[(size_t)row * SEQ + j] = h;
        sum += __half2float(h);
    }
    red[tid] = sum;
    __syncthreads();
#pragma unroll
    for (int s = 128; s > 0; s >>= 1) {
        if (tid < s) red[tid] += red[tid + s];
        __syncthreads();
    }
    if (tid == 0) rinv[row] = 1.0f / red[0];
}

// ---------------- host side --------------------------------------------------
extern "C" void kernel_launch(void* const* d_in, const int* in_sizes, int n_in,
                              void* d_out, int out_size)
{
    const float* x  = (const float*)d_in[0];
    const float* Wq = (const float*)d_in[1];
    const float* Wk = (const float*)d_in[2];
    const float* Wv = (const float*)d_in[3];
    float* out = (float*)d_out;

    __half *x2[2], *Wq2[2], *Wk2[2], *Wv2[2], *Q2[2], *K2[2], *Vt2[2];
    __half *Ph;
    float *V, *P, *rinv, *rowmax;
    for (int i = 0; i < 2; i++) {
        cudaGetSymbolAddress((void**)&x2[i],  g_x2);  x2[i]  += (size_t)i * SEQ * DIM;
        cudaGetSymbolAddress((void**)&Wq2[i], g_Wq2); Wq2[i] += (size_t)i * DIM * DIM;
        cudaGetSymbolAddress((void**)&Wk2[i], g_Wk2); Wk2[i] += (size_t)i * DIM * DIM;
        cudaGetSymbolAddress((void**)&Wv2[i], g_Wv2); Wv2[i] += (size_t)i * DIM * DIM;
        cudaGetSymbolAddress((void**)&Q2[i],  g_Q2);  Q2[i]  += (size_t)i * SEQ * DIM;
        cudaGetSymbolAddress((void**)&K2[i],  g_K2);  K2[i]  += (size_t)i * SEQ * DIM;
        cudaGetSymbolAddress((void**)&Vt2[i], g_Vt2); Vt2[i] += (size_t)i * DIM * SEQ;
    }
    cudaGetSymbolAddress((void**)&Ph,     g_Ph);
    cudaGetSymbolAddress((void**)&V,      g_V);
    cudaGetSymbolAddress((void**)&P,      g_P);
    cudaGetSymbolAddress((void**)&rinv,   g_rinv);
    cudaGetSymbolAddress((void**)&rowmax, g_rowmax);

    auto proj_w64   = hmma_w64<0>;       // merged QKV proj
    auto causal_w64 = hmma_w64<1>;       // QK^T + rowmax

    const int SMW = 2 * 4 * 10240 + 1024;   // 82944 (4 planes x2 stages)
    const int SMP = 2 * 3 * 10240 + 1024;   // 62464 (3 planes x2 stages)
    cudaFuncSetAttribute(proj_w64,    cudaFuncAttributeMaxDynamicSharedMemorySize, SMW);
    cudaFuncSetAttribute(causal_w64,  cudaFuncAttributeMaxDynamicSharedMemorySize, SMW);
    cudaFuncSetAttribute(hmma_pv_w64, cudaFuncAttributeMaxDynamicSharedMemorySize, SMP);

    // 1) operand splits (also resets rowmax to -inf)
    split2_kernel<<<1024, 256>>>(x, (size_t)SEQ * DIM, x2[0], x2[1], rowmax);
    dim3 tb(32, 8);
    tsplitW_kernel<<<dim3(DIM / 32, DIM / 32, 3), tb>>>(Wq, Wk, Wv,
                                                        Wq2[0], Wq2[1], Wk2[0], Wk2[1],
                                                        Wv2[0], Wv2[1]);

    // 2) all three projections in ONE launch (768 CTAs of 128 threads)
    proj_w64<<<dim3(DIM / 128, SEQ / 128, 3), 128, SMW>>>(
        x2[0], x2[1], Wq2[0], Wq2[1], Wk2[0], Wk2[1], Wv2[0], Wv2[1],
        DIM, DIM, DIM, V, Q2[0], Q2[1], K2[0], K2[1], DIM, nullptr);

    // 3) V -> Vt (split2, transposed)
    tsplitV_kernel<<<dim3(DIM / 32, SEQ / 32), tb>>>(V, Vt2[0], Vt2[1]);

    // 4) scaled logits + row maxes (compact triangular grid, 528 CTAs)
    causal_w64<<<dim3(32 * 33 / 2), 128, SMW>>>(
        Q2[0], Q2[1], K2[0], K2[1], nullptr, nullptr, nullptr, nullptr,
        DIM, DIM, DIM, P, nullptr, nullptr, nullptr, nullptr, SEQ, rowmax);

    // 5) single-pass softmax -> fp16 probs + rinv of rounded sum
    softmax_h<<<SEQ, 256>>>(P, rowmax, Ph, rinv);

    // 6) out = (Ph @ V) * rinv, w64 shape, split-K over 2 CTAs (RED combine)
    cudaMemsetAsync(out, 0, (size_t)SEQ * DIM * sizeof(float));
    hmma_pv_w64<<<dim3(DIM / 128, SEQ / 128, 2), 128, SMP>>>(Ph, Vt2[0], Vt2[1],
                                                             out, rinv);
}